// round 4
// baseline (speedup 1.0000x reference)
#include <cuda_runtime.h>
#include <math_constants.h>

#define E_DIM 256
#define T_DIM 1024
#define NH 8
#define HD 32
#define B_DIM 8
#define BHTOT 64   // B*NH

// Scratch (no allocations allowed): 4 x 8MB fp32
__device__ float g_q [BHTOT * T_DIM * HD];
__device__ float g_k [BHTOT * T_DIM * HD];
__device__ float g_v [BHTOT * T_DIM * HD];
__device__ float g_ao[BHTOT * T_DIM * HD];

// ---------------------------------------------------------------------------
// Projection GEMM: Y = W(E,E) @ X(E,T) + bias, per batch b.
// IN_MODE  0: X is [B,E,T]      (raw input, T contiguous)
// IN_MODE  1: X is [BH,T,HD]    (attention output buffer)
// OUT_MODE 0: Y is [B,E,T]      (final output)
// OUT_MODE 1: Y is [BH,T,HD]    (attention operand layout), scaled by `scale`
// Block: 256 threads, 64x64 tile, 4x4 per thread, BK=16.
// ---------------------------------------------------------------------------
template<int IN_MODE, int OUT_MODE>
__global__ __launch_bounds__(256) void proj_kernel(
    const float* __restrict__ X, const float* __restrict__ Wm,
    const float* __restrict__ bias, float* __restrict__ Y, float scale)
{
    const int b  = blockIdx.z;
    const int m0 = blockIdx.y * 64;   // output channel tile
    const int n0 = blockIdx.x * 64;   // token tile
    const int tid = threadIdx.x;
    const int tx = tid & 15, ty = tid >> 4;

    __shared__ float Ws[16][65];  // [k][m], padded (conflict-free stores)
    __shared__ float Xs[16][64];  // [k][n]

    float acc[4][4];
    #pragma unroll
    for (int i = 0; i < 4; i++)
        #pragma unroll
        for (int j = 0; j < 4; j++) acc[i][j] = 0.f;

    for (int k0 = 0; k0 < E_DIM; k0 += 16) {
        // ---- load W tile: 64 rows(m) x 16 cols(k) ----
        #pragma unroll
        for (int jj = 0; jj < 4; jj++) {
            int idx = tid + jj * 256;      // 0..1023
            int c = idx & 15;              // k
            int r = idx >> 4;              // m
            Ws[c][r] = Wm[(m0 + r) * E_DIM + (k0 + c)];
        }
        // ---- load X tile: 16 rows(k) x 64 cols(n) ----
        #pragma unroll
        for (int jj = 0; jj < 4; jj++) {
            int idx = tid + jj * 256;
            int c = idx & 63;              // n (token)
            int r = idx >> 6;              // k (in channel)
            int ich = k0 + r;
            int tok = n0 + c;
            float xv;
            if (IN_MODE == 0)
                xv = X[((size_t)b * E_DIM + ich) * T_DIM + tok];
            else
                xv = X[(((size_t)b * NH + (ich >> 5)) * T_DIM + tok) * HD + (ich & 31)];
            Xs[r][c] = xv;
        }
        __syncthreads();

        #pragma unroll
        for (int kk = 0; kk < 16; kk++) {
            float rm[4];
            #pragma unroll
            for (int i = 0; i < 4; i++) rm[i] = Ws[kk][ty * 4 + i];
            float4 n4 = *(const float4*)&Xs[kk][tx * 4];
            float rn[4] = {n4.x, n4.y, n4.z, n4.w};
            #pragma unroll
            for (int i = 0; i < 4; i++)
                #pragma unroll
                for (int j = 0; j < 4; j++)
                    acc[i][j] += rm[i] * rn[j];
        }
        __syncthreads();
    }

    #pragma unroll
    for (int i = 0; i < 4; i++) {
        int o = m0 + ty * 4 + i;
        float bv = bias[o];
        #pragma unroll
        for (int j = 0; j < 4; j++) {
            int tok = n0 + tx * 4 + j;
            float v = acc[i][j] + bv;
            if (OUT_MODE == 0)
                Y[((size_t)b * E_DIM + o) * T_DIM + tok] = v;
            else
                Y[(((size_t)b * NH + (o >> 5)) * T_DIM + tok) * HD + (o & 31)] = v * scale;
        }
    }
}

// ---------------------------------------------------------------------------
// Fused flash-style attention.
// Q,K,V: [BH, T, HD] (Q pre-scaled by hd^-0.5). mask: [T,S] added to scores.
// One thread owns one query row (q + acc in registers). K/V staged in smem
// tiles of 32 rows; online softmax across S=1024.
// ---------------------------------------------------------------------------
__global__ __launch_bounds__(128) void attn_kernel(
    const float* __restrict__ Q, const float* __restrict__ K,
    const float* __restrict__ V, const float* __restrict__ mask,
    float* __restrict__ O)
{
    const int bh  = blockIdx.y;
    const int tid = threadIdx.x;
    const int t   = blockIdx.x * 128 + tid;

    __shared__ float4 Ks[32][8];   // [s][d/4]
    __shared__ float4 Vs[32][8];

    float4 q[8];
    const float4* qp = (const float4*)(Q + ((size_t)bh * T_DIM + t) * HD);
    #pragma unroll
    for (int i = 0; i < 8; i++) q[i] = qp[i];

    float acc[32];
    #pragma unroll
    for (int d = 0; d < 32; d++) acc[d] = 0.f;
    float mM = -CUDART_INF_F, l = 0.f;

    const float* mrow = mask + (size_t)t * T_DIM;

    for (int s0 = 0; s0 < T_DIM; s0 += 32) {
        __syncthreads();
        {
            const float4* kp = (const float4*)(K + ((size_t)bh * T_DIM + s0) * HD);
            const float4* vp = (const float4*)(V + ((size_t)bh * T_DIM + s0) * HD);
            ((float4*)Ks)[tid]       = kp[tid];
            ((float4*)Ks)[tid + 128] = kp[tid + 128];
            ((float4*)Vs)[tid]       = vp[tid];
            ((float4*)Vs)[tid + 128] = vp[tid + 128];
        }
        __syncthreads();

        float sc[32];
        float tmax = -CUDART_INF_F;
        #pragma unroll
        for (int s = 0; s < 32; s++) {
            float dotv = 0.f;
            #pragma unroll
            for (int c = 0; c < 8; c++) {
                float4 kv = Ks[s][c];   // broadcast across warp
                dotv += q[c].x * kv.x + q[c].y * kv.y
                      + q[c].z * kv.z + q[c].w * kv.w;
            }
            dotv += __ldg(&mrow[s0 + s]);
            sc[s] = dotv;
            tmax = fmaxf(tmax, dotv);
        }

        float mnew = fmaxf(mM, tmax);
        float corr = __expf(mM - mnew);   // exp(-inf)=0 handles first tile
        l *= corr;
        #pragma unroll
        for (int d = 0; d < 32; d++) acc[d] *= corr;

        #pragma unroll
        for (int s = 0; s < 32; s++) {
            float p = __expf(sc[s] - mnew);
            l += p;
            #pragma unroll
            for (int c = 0; c < 8; c++) {
                float4 vv = Vs[s][c];   // broadcast
                acc[c * 4 + 0] += p * vv.x;
                acc[c * 4 + 1] += p * vv.y;
                acc[c * 4 + 2] += p * vv.z;
                acc[c * 4 + 3] += p * vv.w;
            }
        }
        mM = mnew;
    }

    float inv = 1.f / l;
    float4* op = (float4*)(O + ((size_t)bh * T_DIM + t) * HD);
    #pragma unroll
    for (int c = 0; c < 8; c++) {
        float4 o4;
        o4.x = acc[c * 4 + 0] * inv;
        o4.y = acc[c * 4 + 1] * inv;
        o4.z = acc[c * 4 + 2] * inv;
        o4.w = acc[c * 4 + 3] * inv;
        op[c] = o4;
    }
}

// ---------------------------------------------------------------------------
extern "C" void kernel_launch(void* const* d_in, const int* in_sizes, int n_in,
                              void* d_out, int out_size)
{
    // metadata order (dict insertion order of setup_inputs):
    //   0:query 1:key 2:value 3:attn_mask
    //   4:Wq 5:Wk 6:Wv 7:Wo        (all weights first!)
    //   8:bq 9:bk 10:bv 11:bo      (then all biases)
    const float* query = (const float*)d_in[0];
    const float* key   = (const float*)d_in[1];
    const float* value = (const float*)d_in[2];
    const float* mask  = (const float*)d_in[3];
    const float* Wq    = (const float*)d_in[4];
    const float* Wk    = (const float*)d_in[5];
    const float* Wv    = (const float*)d_in[6];
    const float* Wo    = (const float*)d_in[7];
    const float* bq    = (const float*)d_in[8];
    const float* bk    = (const float*)d_in[9];
    const float* bv    = (const float*)d_in[10];
    const float* bo    = (const float*)d_in[11];
    float* out = (float*)d_out;

    static float *q_buf = nullptr, *k_buf = nullptr, *v_buf = nullptr, *ao_buf = nullptr;
    if (!q_buf) {
        void* p;
        cudaGetSymbolAddress(&p, g_q);  q_buf  = (float*)p;
        cudaGetSymbolAddress(&p, g_k);  k_buf  = (float*)p;
        cudaGetSymbolAddress(&p, g_v);  v_buf  = (float*)p;
        cudaGetSymbolAddress(&p, g_ao); ao_buf = (float*)p;
    }

    dim3 pg(T_DIM / 64, E_DIM / 64, B_DIM);
    dim3 pb(256);
    const float scale = 0.17677669529663687f;  // 32^-0.5, folded into Q proj

    proj_kernel<0, 1><<<pg, pb>>>(query, Wq, bq, q_buf, scale);
    proj_kernel<0, 1><<<pg, pb>>>(key,   Wk, bk, k_buf, 1.0f);
    proj_kernel<0, 1><<<pg, pb>>>(value, Wv, bv, v_buf, 1.0f);

    dim3 ag(T_DIM / 128, BHTOT);
    attn_kernel<<<ag, 128>>>(q_buf, k_buf, v_buf, mask, ao_buf);

    proj_kernel<1, 0><<<pg, pb>>>(ao_buf, Wo, bo, out, 1.0f);
}

// round 5
// speedup vs baseline: 1.8738x; 1.8738x over previous
#include <cuda_runtime.h>
#include <math_constants.h>

#define E_DIM 256
#define T_DIM 1024
#define NH 8
#define HD 32
#define B_DIM 8
#define BHTOT 64   // B*NH

// Scratch (no allocations allowed): 4 x 8MB fp32
__device__ float g_q [BHTOT * T_DIM * HD];
__device__ float g_k [BHTOT * T_DIM * HD];
__device__ float g_v [BHTOT * T_DIM * HD];
__device__ float g_ao[BHTOT * T_DIM * HD];

// ---------------------------------------------------------------------------
// Projection GEMM: Y = W(E,E) @ X(E,T) + bias, per batch b.
// IN_MODE  0: X is [B,E,T]   IN_MODE 1: X is [BH,T,HD]
// OUT_MODE 0: Y is [B,E,T]   OUT_MODE 1: Y is [BH,T,HD] (scaled)
// 256 threads, 64x64 tile, 4x4 per thread, BK=16.
// ---------------------------------------------------------------------------
template<int IN_MODE, int OUT_MODE>
__global__ __launch_bounds__(256) void proj_kernel(
    const float* __restrict__ X, const float* __restrict__ Wm,
    const float* __restrict__ bias, float* __restrict__ Y, float scale)
{
    const int b  = blockIdx.z;
    const int m0 = blockIdx.y * 64;
    const int n0 = blockIdx.x * 64;
    const int tid = threadIdx.x;
    const int tx = tid & 15, ty = tid >> 4;

    __shared__ float Ws[16][68];  // [k][m], 68-pad: float4 rows 16B-aligned
    __shared__ float Xs[16][68];  // [k][n]

    float acc[4][4];
    #pragma unroll
    for (int i = 0; i < 4; i++)
        #pragma unroll
        for (int j = 0; j < 4; j++) acc[i][j] = 0.f;

    for (int k0 = 0; k0 < E_DIM; k0 += 16) {
        #pragma unroll
        for (int jj = 0; jj < 4; jj++) {
            int idx = tid + jj * 256;
            int c = idx & 15;              // k
            int r = idx >> 4;              // m
            Ws[c][r] = Wm[(m0 + r) * E_DIM + (k0 + c)];
        }
        #pragma unroll
        for (int jj = 0; jj < 4; jj++) {
            int idx = tid + jj * 256;
            int c = idx & 63;              // n (token)
            int r = idx >> 6;              // k
            int ich = k0 + r;
            int tok = n0 + c;
            float xv;
            if (IN_MODE == 0)
                xv = X[((size_t)b * E_DIM + ich) * T_DIM + tok];
            else
                xv = X[(((size_t)b * NH + (ich >> 5)) * T_DIM + tok) * HD + (ich & 31)];
            Xs[r][c] = xv;
        }
        __syncthreads();

        #pragma unroll
        for (int kk = 0; kk < 16; kk++) {
            float4 m4 = *(const float4*)&Ws[kk][ty * 4];   // broadcast LDS.128
            float4 n4 = *(const float4*)&Xs[kk][tx * 4];
            float rm[4] = {m4.x, m4.y, m4.z, m4.w};
            float rn[4] = {n4.x, n4.y, n4.z, n4.w};
            #pragma unroll
            for (int i = 0; i < 4; i++)
                #pragma unroll
                for (int j = 0; j < 4; j++)
                    acc[i][j] += rm[i] * rn[j];
        }
        __syncthreads();
    }

    #pragma unroll
    for (int i = 0; i < 4; i++) {
        int o = m0 + ty * 4 + i;
        float bv = bias[o];
        #pragma unroll
        for (int j = 0; j < 4; j++) {
            int tok = n0 + tx * 4 + j;
            float v = acc[i][j] + bv;
            if (OUT_MODE == 0)
                Y[((size_t)b * E_DIM + o) * T_DIM + tok] = v;
            else
                Y[(((size_t)b * NH + (o >> 5)) * T_DIM + tok) * HD + (o & 31)] = v * scale;
        }
    }
}

// ---------------------------------------------------------------------------
// Register-tiled flash attention.
// Block: 256 threads, 64 queries, key tiles of 64. Two micro-GEMMs:
//   GEMM1: S(64x64) = Q(64x32) K^T(32x64), per-thread 4x4 tile (tx=key grp, ty=q grp)
//   GEMM2: O(64x32) += P(64x64) V(64x32), per-thread 4q x 2d tile
// Online softmax; row state replicated over the 16 tx-threads of a q row,
// kept consistent via shfl_xor reductions.
// ---------------------------------------------------------------------------
__global__ __launch_bounds__(256) void attn_kernel(
    const float* __restrict__ Q, const float* __restrict__ K,
    const float* __restrict__ V, const float* __restrict__ mask,
    float* __restrict__ O)
{
    const int bh = blockIdx.y;
    const int q0 = blockIdx.x * 64;
    const int tid = threadIdx.x;
    const int tx = tid & 15, ty = tid >> 4;

    __shared__ float  Qs[32][64];      // [k][q]
    __shared__ float  Ks[32][68];      // [k][s], padded
    __shared__ float4 Vs4[64 * 8];     // [s][d/4]
    __shared__ float4 Ps4[64][16];     // [s][swizzled q/4]

    // ---- load Q tile transposed (once) ----
    {
        int s  = tid >> 2;
        int kc = (tid & 3) * 8;
        const float4* g = (const float4*)(Q + ((size_t)bh * T_DIM + q0 + s) * HD + kc);
        float4 a = g[0], b = g[1];
        Qs[kc + 0][s] = a.x; Qs[kc + 1][s] = a.y; Qs[kc + 2][s] = a.z; Qs[kc + 3][s] = a.w;
        Qs[kc + 4][s] = b.x; Qs[kc + 5][s] = b.y; Qs[kc + 6][s] = b.z; Qs[kc + 7][s] = b.w;
    }

    float m_[4], l_[4], o_[4][2];
    #pragma unroll
    for (int i = 0; i < 4; i++) {
        m_[i] = -CUDART_INF_F; l_[i] = 0.f;
        o_[i][0] = 0.f; o_[i][1] = 0.f;
    }

    for (int s0 = 0; s0 < T_DIM; s0 += 64) {
        __syncthreads();   // prev tile's Ps/Vs reads done before overwrite
        // ---- load K tile transposed ----
        {
            int s  = tid >> 2;
            int kc = (tid & 3) * 8;
            const float4* g = (const float4*)(K + ((size_t)bh * T_DIM + s0 + s) * HD + kc);
            float4 a = g[0], b = g[1];
            Ks[kc + 0][s] = a.x; Ks[kc + 1][s] = a.y; Ks[kc + 2][s] = a.z; Ks[kc + 3][s] = a.w;
            Ks[kc + 4][s] = b.x; Ks[kc + 5][s] = b.y; Ks[kc + 6][s] = b.z; Ks[kc + 7][s] = b.w;
        }
        // ---- load V tile (direct, s-major) ----
        {
            const float4* vg = (const float4*)(V + ((size_t)bh * T_DIM + s0) * HD);
            Vs4[tid]       = vg[tid];
            Vs4[tid + 256] = vg[tid + 256];
        }
        __syncthreads();

        // ---- GEMM1: 4x4 score tile ----
        float acc[4][4];
        #pragma unroll
        for (int i = 0; i < 4; i++)
            #pragma unroll
            for (int j = 0; j < 4; j++) acc[i][j] = 0.f;

        #pragma unroll
        for (int kk = 0; kk < 32; kk++) {
            float4 rq4 = *(const float4*)&Qs[kk][ty * 4];   // broadcast
            float4 rk4 = *(const float4*)&Ks[kk][tx * 4];
            float rq[4] = {rq4.x, rq4.y, rq4.z, rq4.w};
            float rk[4] = {rk4.x, rk4.y, rk4.z, rk4.w};
            #pragma unroll
            for (int i = 0; i < 4; i++)
                #pragma unroll
                for (int j = 0; j < 4; j++)
                    acc[i][j] += rq[i] * rk[j];
        }

        // ---- + mask ----
        #pragma unroll
        for (int i = 0; i < 4; i++) {
            float4 mk = *(const float4*)&mask[(size_t)(q0 + ty * 4 + i) * T_DIM + s0 + tx * 4];
            acc[i][0] += mk.x; acc[i][1] += mk.y; acc[i][2] += mk.z; acc[i][3] += mk.w;
        }

        // ---- online softmax (row reductions over tx group via shfl) ----
        #pragma unroll
        for (int i = 0; i < 4; i++) {
            float rmax = fmaxf(fmaxf(acc[i][0], acc[i][1]), fmaxf(acc[i][2], acc[i][3]));
            #pragma unroll
            for (int mset = 1; mset < 16; mset <<= 1)
                rmax = fmaxf(rmax, __shfl_xor_sync(0xffffffffu, rmax, mset));
            float mnew = fmaxf(m_[i], rmax);
            float corr = __expf(m_[i] - mnew);
            #pragma unroll
            for (int j = 0; j < 4; j++) acc[i][j] = __expf(acc[i][j] - mnew);
            float rsum = acc[i][0] + acc[i][1] + acc[i][2] + acc[i][3];
            #pragma unroll
            for (int mset = 1; mset < 16; mset <<= 1)
                rsum += __shfl_xor_sync(0xffffffffu, rsum, mset);
            l_[i] = l_[i] * corr + rsum;
            o_[i][0] *= corr; o_[i][1] *= corr;
            m_[i] = mnew;
        }

        // ---- write P tile (swizzled: col4 = ty ^ (s>>2) = ty ^ tx) ----
        #pragma unroll
        for (int j = 0; j < 4; j++)
            Ps4[tx * 4 + j][ty ^ tx] = make_float4(acc[0][j], acc[1][j], acc[2][j], acc[3][j]);
        __syncthreads();

        // ---- GEMM2: O[4q x 2d] += P[64] V ----
        #pragma unroll
        for (int ss = 0; ss < 64; ss++) {
            float4 pq = Ps4[ss][ty ^ (ss >> 2)];            // broadcast
            float2 vv = *(const float2*)((const float*)&Vs4[ss * 8] + tx * 2);
            float pp[4] = {pq.x, pq.y, pq.z, pq.w};
            #pragma unroll
            for (int i = 0; i < 4; i++) {
                o_[i][0] += pp[i] * vv.x;
                o_[i][1] += pp[i] * vv.y;
            }
        }
    }

    // ---- epilogue ----
    #pragma unroll
    for (int i = 0; i < 4; i++) {
        float inv = 1.f / l_[i];
        float2 r;
        r.x = o_[i][0] * inv;
        r.y = o_[i][1] * inv;
        *(float2*)(O + ((size_t)bh * T_DIM + q0 + ty * 4 + i) * HD + tx * 2) = r;
    }
}

// ---------------------------------------------------------------------------
extern "C" void kernel_launch(void* const* d_in, const int* in_sizes, int n_in,
                              void* d_out, int out_size)
{
    // metadata order: 0:query 1:key 2:value 3:attn_mask
    //                 4:Wq 5:Wk 6:Wv 7:Wo  8:bq 9:bk 10:bv 11:bo
    const float* query = (const float*)d_in[0];
    const float* key   = (const float*)d_in[1];
    const float* value = (const float*)d_in[2];
    const float* mask  = (const float*)d_in[3];
    const float* Wq    = (const float*)d_in[4];
    const float* Wk    = (const float*)d_in[5];
    const float* Wv    = (const float*)d_in[6];
    const float* Wo    = (const float*)d_in[7];
    const float* bq    = (const float*)d_in[8];
    const float* bk    = (const float*)d_in[9];
    const float* bv    = (const float*)d_in[10];
    const float* bo    = (const float*)d_in[11];
    float* out = (float*)d_out;

    static float *q_buf = nullptr, *k_buf = nullptr, *v_buf = nullptr, *ao_buf = nullptr;
    if (!q_buf) {
        void* p;
        cudaGetSymbolAddress(&p, g_q);  q_buf  = (float*)p;
        cudaGetSymbolAddress(&p, g_k);  k_buf  = (float*)p;
        cudaGetSymbolAddress(&p, g_v);  v_buf  = (float*)p;
        cudaGetSymbolAddress(&p, g_ao); ao_buf = (float*)p;
    }

    dim3 pg(T_DIM / 64, E_DIM / 64, B_DIM);
    dim3 pb(256);
    const float scale = 0.17677669529663687f;  // 32^-0.5, folded into Q proj

    proj_kernel<0, 1><<<pg, pb>>>(query, Wq, bq, q_buf, scale);
    proj_kernel<0, 1><<<pg, pb>>>(key,   Wk, bk, k_buf, 1.0f);
    proj_kernel<0, 1><<<pg, pb>>>(value, Wv, bv, v_buf, 1.0f);

    dim3 ag(T_DIM / 64, BHTOT);
    attn_kernel<<<ag, 256>>>(q_buf, k_buf, v_buf, mask, ao_buf);

    proj_kernel<1, 0><<<pg, pb>>>(ao_buf, Wo, bo, out, 1.0f);
}

// round 10
// speedup vs baseline: 2.4600x; 1.3128x over previous
#include <cuda_runtime.h>
#include <math_constants.h>
#include <cstdint>

#define E_DIM 256
#define T_DIM 1024
#define NH 8
#define HD 32
#define B_DIM 8
#define BHTOT 64   // B*NH

// Scratch (no allocations allowed): 4 x 8MB fp32
__device__ float g_q [BHTOT * T_DIM * HD];
__device__ float g_k [BHTOT * T_DIM * HD];
__device__ float g_v [BHTOT * T_DIM * HD];
__device__ float g_ao[BHTOT * T_DIM * HD];

// ===========================================================================
// tf32 warp MMA helpers (legacy mma.sync path — valid on base sm_103 target)
// ===========================================================================
__device__ __forceinline__ uint32_t f2tf(float x) {
    uint32_t r;
    asm("cvt.rna.tf32.f32 %0, %1;" : "=r"(r) : "f"(x));
    return r;
}

// D(16x8) += A(16x8) * B(8x8); A row-major frags, B col-major frags.
__device__ __forceinline__ void mma16n8k8(float c[4], const uint32_t a[4],
                                          uint32_t b0, uint32_t b1) {
    asm volatile(
        "mma.sync.aligned.m16n8k8.row.col.f32.tf32.tf32.f32 "
        "{%0,%1,%2,%3}, {%4,%5,%6,%7}, {%8,%9}, {%0,%1,%2,%3};"
        : "+f"(c[0]), "+f"(c[1]), "+f"(c[2]), "+f"(c[3])
        : "r"(a[0]), "r"(a[1]), "r"(a[2]), "r"(a[3]), "r"(b0), "r"(b1));
}

// ---------------------------------------------------------------------------
// Projection GEMM (unchanged): Y = W(E,E) @ X(E,T) + bias, per batch b.
// ---------------------------------------------------------------------------
template<int IN_MODE, int OUT_MODE>
__global__ __launch_bounds__(256) void proj_kernel(
    const float* __restrict__ X, const float* __restrict__ Wm,
    const float* __restrict__ bias, float* __restrict__ Y, float scale)
{
    const int b  = blockIdx.z;
    const int m0 = blockIdx.y * 64;
    const int n0 = blockIdx.x * 64;
    const int tid = threadIdx.x;
    const int tx = tid & 15, ty = tid >> 4;

    __shared__ float Ws[16][68];
    __shared__ float Xs[16][68];

    float acc[4][4];
    #pragma unroll
    for (int i = 0; i < 4; i++)
        #pragma unroll
        for (int j = 0; j < 4; j++) acc[i][j] = 0.f;

    for (int k0 = 0; k0 < E_DIM; k0 += 16) {
        #pragma unroll
        for (int jj = 0; jj < 4; jj++) {
            int idx = tid + jj * 256;
            int c = idx & 15;
            int r = idx >> 4;
            Ws[c][r] = Wm[(m0 + r) * E_DIM + (k0 + c)];
        }
        #pragma unroll
        for (int jj = 0; jj < 4; jj++) {
            int idx = tid + jj * 256;
            int c = idx & 63;
            int r = idx >> 6;
            int ich = k0 + r;
            int tok = n0 + c;
            float xv;
            if (IN_MODE == 0)
                xv = X[((size_t)b * E_DIM + ich) * T_DIM + tok];
            else
                xv = X[(((size_t)b * NH + (ich >> 5)) * T_DIM + tok) * HD + (ich & 31)];
            Xs[r][c] = xv;
        }
        __syncthreads();

        #pragma unroll
        for (int kk = 0; kk < 16; kk++) {
            float4 m4 = *(const float4*)&Ws[kk][ty * 4];
            float4 n4 = *(const float4*)&Xs[kk][tx * 4];
            float rm[4] = {m4.x, m4.y, m4.z, m4.w};
            float rn[4] = {n4.x, n4.y, n4.z, n4.w};
            #pragma unroll
            for (int i = 0; i < 4; i++)
                #pragma unroll
                for (int j = 0; j < 4; j++)
                    acc[i][j] += rm[i] * rn[j];
        }
        __syncthreads();
    }

    #pragma unroll
    for (int i = 0; i < 4; i++) {
        int o = m0 + ty * 4 + i;
        float bv = bias[o];
        #pragma unroll
        for (int j = 0; j < 4; j++) {
            int tok = n0 + tx * 4 + j;
            float v = acc[i][j] + bv;
            if (OUT_MODE == 0)
                Y[((size_t)b * E_DIM + o) * T_DIM + tok] = v;
            else
                Y[(((size_t)b * NH + (o >> 5)) * T_DIM + tok) * HD + (o & 31)] = v * scale;
        }
    }
}

// ---------------------------------------------------------------------------
// Warp-MMA (tf32) flash attention.
// Block = 128 threads = 4 warps; q-tile 64 rows (warp w owns rows w*16..+16).
// Per 64-key tile:
//   MMA1: S(16x64) = Q(16x32)*K^T   (8 n-tiles x 4 k-steps)
//   online softmax on C frags (row state per lane-quad, shfl_xor 1,2)
//   P -> per-warp smem, re-read as A frags
//   MMA2: O(16x32) += P(16x64)*V    (4 n-tiles x 8 k-steps)
// Q frags live in registers across all tiles; O accumulated in C frags.
// ---------------------------------------------------------------------------
__global__ __launch_bounds__(128) void attn_mma_kernel(
    const float* __restrict__ Q, const float* __restrict__ K,
    const float* __restrict__ V, const float* __restrict__ mask,
    float* __restrict__ O)
{
    __shared__ float Ks[64][40];      // [key s][dim k]  (8*grp+tig bank map)
    __shared__ float Vs[64][40];      // [key s][dim d]
    __shared__ float Ps[4][16][68];   // per-warp P tile [q row][s]

    const int bh  = blockIdx.y;
    const int q0  = blockIdx.x * 64;
    const int tid = threadIdx.x;
    const int w   = tid >> 5;
    const int l   = tid & 31;
    const int grp = l >> 2;    // 0..7
    const int tig = l & 3;     // 0..3

    // ---- Q fragments (held for the whole kernel) ----
    uint32_t qa[4][4];
    {
        const float* Qb = Q + ((size_t)bh * T_DIM + q0 + w * 16) * HD;
        #pragma unroll
        for (int ks = 0; ks < 4; ks++) {
            qa[ks][0] = f2tf(Qb[(size_t)grp       * HD + ks * 8 + tig]);
            qa[ks][1] = f2tf(Qb[(size_t)(grp + 8) * HD + ks * 8 + tig]);
            qa[ks][2] = f2tf(Qb[(size_t)grp       * HD + ks * 8 + tig + 4]);
            qa[ks][3] = f2tf(Qb[(size_t)(grp + 8) * HD + ks * 8 + tig + 4]);
        }
    }

    float o_[4][4];
    #pragma unroll
    for (int nt = 0; nt < 4; nt++)
        #pragma unroll
        for (int j = 0; j < 4; j++) o_[nt][j] = 0.f;
    float mA = -CUDART_INF_F, mB = -CUDART_INF_F, lA = 0.f, lB = 0.f;

    const float* mrA = mask + (size_t)(q0 + w * 16 + grp) * T_DIM;
    const float* mrB = mrA + 8 * T_DIM;

    for (int s0 = 0; s0 < T_DIM; s0 += 64) {
        __syncthreads();   // prior tile's Ks/Vs reads complete
        // ---- cooperative K/V tile load (natural [s][dim] layout) ----
        {
            int s = tid >> 1, hf = (tid & 1) * 16;
            const float4* kg = (const float4*)(K + ((size_t)bh * T_DIM + s0 + s) * HD + hf);
            const float4* vg = (const float4*)(V + ((size_t)bh * T_DIM + s0 + s) * HD + hf);
            #pragma unroll
            for (int j = 0; j < 4; j++) {
                *(float4*)&Ks[s][hf + j * 4] = kg[j];
                *(float4*)&Vs[s][hf + j * 4] = vg[j];
            }
        }
        __syncthreads();

        // ---- MMA1: scores ----
        float sc[8][4];
        #pragma unroll
        for (int nt = 0; nt < 8; nt++) {
            #pragma unroll
            for (int j = 0; j < 4; j++) sc[nt][j] = 0.f;
            #pragma unroll
            for (int ks = 0; ks < 4; ks++) {
                uint32_t b0 = f2tf(Ks[nt * 8 + grp][ks * 8 + tig]);
                uint32_t b1 = f2tf(Ks[nt * 8 + grp][ks * 8 + tig + 4]);
                mma16n8k8(sc[nt], qa[ks], b0, b1);
            }
            // mask add (fp32)
            float2 mk0 = __ldg((const float2*)&mrA[s0 + nt * 8 + 2 * tig]);
            float2 mk1 = __ldg((const float2*)&mrB[s0 + nt * 8 + 2 * tig]);
            sc[nt][0] += mk0.x; sc[nt][1] += mk0.y;
            sc[nt][2] += mk1.x; sc[nt][3] += mk1.y;
        }

        // ---- online softmax (rows rA: c0,c1; rB: c2,c3) ----
        float mxA = -CUDART_INF_F, mxB = -CUDART_INF_F;
        #pragma unroll
        for (int nt = 0; nt < 8; nt++) {
            mxA = fmaxf(mxA, fmaxf(sc[nt][0], sc[nt][1]));
            mxB = fmaxf(mxB, fmaxf(sc[nt][2], sc[nt][3]));
        }
        #pragma unroll
        for (int ms = 1; ms < 4; ms <<= 1) {
            mxA = fmaxf(mxA, __shfl_xor_sync(0xffffffffu, mxA, ms));
            mxB = fmaxf(mxB, __shfl_xor_sync(0xffffffffu, mxB, ms));
        }
        float mnA = fmaxf(mA, mxA), mnB = fmaxf(mB, mxB);
        float cA = __expf(mA - mnA), cB = __expf(mB - mnB);

        float sumA = 0.f, sumB = 0.f;
        #pragma unroll
        for (int nt = 0; nt < 8; nt++) {
            float p0 = __expf(sc[nt][0] - mnA);
            float p1 = __expf(sc[nt][1] - mnA);
            float p2 = __expf(sc[nt][2] - mnB);
            float p3 = __expf(sc[nt][3] - mnB);
            sumA += p0 + p1;  sumB += p2 + p3;
            *(float2*)&Ps[w][grp    ][nt * 8 + 2 * tig] = make_float2(p0, p1);
            *(float2*)&Ps[w][grp + 8][nt * 8 + 2 * tig] = make_float2(p2, p3);
        }
        #pragma unroll
        for (int ms = 1; ms < 4; ms <<= 1) {
            sumA += __shfl_xor_sync(0xffffffffu, sumA, ms);
            sumB += __shfl_xor_sync(0xffffffffu, sumB, ms);
        }
        lA = lA * cA + sumA;  mA = mnA;
        lB = lB * cB + sumB;  mB = mnB;

        #pragma unroll
        for (int nt = 0; nt < 4; nt++) {
            o_[nt][0] *= cA; o_[nt][1] *= cA;
            o_[nt][2] *= cB; o_[nt][3] *= cB;
        }
        __syncwarp();   // P visible to all lanes of this warp

        // ---- MMA2: O += P V ----
        #pragma unroll
        for (int ks = 0; ks < 8; ks++) {
            uint32_t pa[4];
            pa[0] = f2tf(Ps[w][grp    ][ks * 8 + tig]);
            pa[1] = f2tf(Ps[w][grp + 8][ks * 8 + tig]);
            pa[2] = f2tf(Ps[w][grp    ][ks * 8 + tig + 4]);
            pa[3] = f2tf(Ps[w][grp + 8][ks * 8 + tig + 4]);
            #pragma unroll
            for (int nt = 0; nt < 4; nt++) {
                uint32_t b0 = f2tf(Vs[ks * 8 + tig    ][nt * 8 + grp]);
                uint32_t b1 = f2tf(Vs[ks * 8 + tig + 4][nt * 8 + grp]);
                mma16n8k8(o_[nt], pa, b0, b1);
            }
        }
        __syncwarp();   // P reads complete before next tile overwrites
    }

    // ---- epilogue ----
    float iA = 1.f / lA, iB = 1.f / lB;
    float* OrA = O + ((size_t)bh * T_DIM + q0 + w * 16 + grp) * HD;
    float* OrB = OrA + 8 * HD;
    #pragma unroll
    for (int nt = 0; nt < 4; nt++) {
        *(float2*)&OrA[nt * 8 + 2 * tig] = make_float2(o_[nt][0] * iA, o_[nt][1] * iA);
        *(float2*)&OrB[nt * 8 + 2 * tig] = make_float2(o_[nt][2] * iB, o_[nt][3] * iB);
    }
}

// ---------------------------------------------------------------------------
extern "C" void kernel_launch(void* const* d_in, const int* in_sizes, int n_in,
                              void* d_out, int out_size)
{
    // metadata order: 0:query 1:key 2:value 3:attn_mask
    //                 4:Wq 5:Wk 6:Wv 7:Wo  8:bq 9:bk 10:bv 11:bo
    const float* query = (const float*)d_in[0];
    const float* key   = (const float*)d_in[1];
    const float* value = (const float*)d_in[2];
    const float* mask  = (const float*)d_in[3];
    const float* Wq    = (const float*)d_in[4];
    const float* Wk    = (const float*)d_in[5];
    const float* Wv    = (const float*)d_in[6];
    const float* Wo    = (const float*)d_in[7];
    const float* bq    = (const float*)d_in[8];
    const float* bk    = (const float*)d_in[9];
    const float* bv    = (const float*)d_in[10];
    const float* bo    = (const float*)d_in[11];
    float* out = (float*)d_out;

    static float *q_buf = nullptr, *k_buf = nullptr, *v_buf = nullptr, *ao_buf = nullptr;
    if (!q_buf) {
        void* p;
        cudaGetSymbolAddress(&p, g_q);  q_buf  = (float*)p;
        cudaGetSymbolAddress(&p, g_k);  k_buf  = (float*)p;
        cudaGetSymbolAddress(&p, g_v);  v_buf  = (float*)p;
        cudaGetSymbolAddress(&p, g_ao); ao_buf = (float*)p;
    }

    dim3 pg(T_DIM / 64, E_DIM / 64, B_DIM);
    dim3 pb(256);
    const float scale = 0.17677669529663687f;  // 32^-0.5, folded into Q proj

    proj_kernel<0, 1><<<pg, pb>>>(query, Wq, bq, q_buf, scale);
    proj_kernel<0, 1><<<pg, pb>>>(key,   Wk, bk, k_buf, 1.0f);
    proj_kernel<0, 1><<<pg, pb>>>(value, Wv, bv, v_buf, 1.0f);

    dim3 ag(T_DIM / 64, BHTOT);
    attn_mma_kernel<<<ag, 128>>>(q_buf, k_buf, v_buf, mask, ao_buf);

    proj_kernel<1, 0><<<pg, pb>>>(ao_buf, Wo, bo, out, 1.0f);
}

// round 11
// speedup vs baseline: 2.8554x; 1.1607x over previous
#include <cuda_runtime.h>
#include <math_constants.h>
#include <cstdint>

#define E_DIM 256
#define T_DIM 1024
#define NH 8
#define HD 32
#define B_DIM 8
#define BHTOT 64   // B*NH

// Scratch (no allocations allowed): 4 x 8MB fp32
__device__ float g_q [BHTOT * T_DIM * HD];
__device__ float g_k [BHTOT * T_DIM * HD];
__device__ float g_v [BHTOT * T_DIM * HD];
__device__ float g_ao[BHTOT * T_DIM * HD];

// ===========================================================================
// tf32 warp MMA helpers
// ===========================================================================
__device__ __forceinline__ uint32_t f2tf(float x) {
    uint32_t r;
    asm("cvt.rna.tf32.f32 %0, %1;" : "=r"(r) : "f"(x));
    return r;
}

__device__ __forceinline__ void mma16n8k8(float c[4], const uint32_t a[4],
                                          uint32_t b0, uint32_t b1) {
    asm volatile(
        "mma.sync.aligned.m16n8k8.row.col.f32.tf32.tf32.f32 "
        "{%0,%1,%2,%3}, {%4,%5,%6,%7}, {%8,%9}, {%0,%1,%2,%3};"
        : "+f"(c[0]), "+f"(c[1]), "+f"(c[2]), "+f"(c[3])
        : "r"(a[0]), "r"(a[1]), "r"(a[2]), "r"(a[3]), "r"(b0), "r"(b1));
}

// paired-k position: within each aligned 8-block store order (0,4),(1,5),(2,6),(3,7)
__device__ __forceinline__ int pairpos(int k) {
    return (k & ~7) | ((k & 3) << 1) | ((k >> 2) & 1);
}

// ---------------------------------------------------------------------------
// Projection GEMM via tf32 mma: Y = W(E,E) @ X(E,T) + bias (then *scale).
// Block 256 thr (8 warps), tile M=64 x N=256, warp 32x64, K-chunks of 32.
// FUSED=1: blockIdx.z = which*8 + b (QKV in one launch).
// IN_MODE  0: X is [B,E,T]    1: X is [BH,T,HD]
// OUT_MODE 0: Y is [B,E,T]    1: Y is [BH,T,HD] (scaled)
// ---------------------------------------------------------------------------
template<int IN_MODE, int OUT_MODE, int FUSED>
__global__ __launch_bounds__(256) void proj_mma_kernel(
    const float* __restrict__ X0, const float* __restrict__ X1, const float* __restrict__ X2,
    const float* __restrict__ W0, const float* __restrict__ W1, const float* __restrict__ W2,
    const float* __restrict__ c0, const float* __restrict__ c1, const float* __restrict__ c2,
    float* __restrict__ Y0, float* __restrict__ Y1, float* __restrict__ Y2,
    float scale0)
{
    const int zz = blockIdx.z;
    const int b     = FUSED ? (zz & 7) : zz;
    const int which = FUSED ? (zz >> 3) : 0;
    const float* X    = (which == 0) ? X0 : (which == 1) ? X1 : X2;
    const float* Wm   = (which == 0) ? W0 : (which == 1) ? W1 : W2;
    const float* bias = (which == 0) ? c0 : (which == 1) ? c1 : c2;
    float*       Y    = (which == 0) ? Y0 : (which == 1) ? Y1 : Y2;
    const float scale = (which == 0) ? scale0 : 1.0f;

    const int m0 = blockIdx.y * 64;
    const int n0 = blockIdx.x * 256;
    const int tid = threadIdx.x;
    const int w = tid >> 5, l = tid & 31;
    const int wm = w >> 2, wn = w & 3;
    const int grp = l >> 2, tig = l & 3;

    __shared__ __align__(16) float Ws[64][40];    // [m][k paired], tf32 bits
    __shared__ __align__(16) float Xs[256][40];   // [n][k paired], tf32 bits

    float acc[2][8][4];
    #pragma unroll
    for (int mt = 0; mt < 2; mt++)
        #pragma unroll
        for (int nt = 0; nt < 8; nt++)
            #pragma unroll
            for (int j = 0; j < 4; j++) acc[mt][nt][j] = 0.f;

    for (int k0 = 0; k0 < E_DIM; k0 += 32) {
        __syncthreads();
        // ---- stage W tile 64x32 ----
        {
            int m = tid >> 2, kq = (tid & 3) * 8;
            const float4* wg = (const float4*)(Wm + (size_t)(m0 + m) * E_DIM + k0 + kq);
            float4 w0 = wg[0], w1 = wg[1];
            float wa[8] = {w0.x, w0.y, w0.z, w0.w, w1.x, w1.y, w1.z, w1.w};
            #pragma unroll
            for (int i = 0; i < 8; i++)
                Ws[m][pairpos(kq + i)] = __uint_as_float(f2tf(wa[i]));
        }
        // ---- stage X tile 32k x 256n ----
        if (IN_MODE == 0) {
            #pragma unroll
            for (int p = 0; p < 8; p++) {
                int k = (tid >> 6) + p * 4;
                int n = (tid & 63) * 4;
                float4 xv = *(const float4*)&X[((size_t)b * E_DIM + k0 + k) * T_DIM + n0 + n];
                int pc = pairpos(k);
                Xs[n + 0][pc] = __uint_as_float(f2tf(xv.x));
                Xs[n + 1][pc] = __uint_as_float(f2tf(xv.y));
                Xs[n + 2][pc] = __uint_as_float(f2tf(xv.z));
                Xs[n + 3][pc] = __uint_as_float(f2tf(xv.w));
            }
        } else {
            int head = k0 >> 5;
            #pragma unroll
            for (int p = 0; p < 8; p++) {
                int tok = (tid >> 3) + p * 32;
                int dq  = (tid & 7) * 4;
                float4 xv = *(const float4*)&X[(((size_t)b * NH + head) * T_DIM + n0 + tok) * HD + dq];
                float xa[4] = {xv.x, xv.y, xv.z, xv.w};
                #pragma unroll
                for (int i = 0; i < 4; i++)
                    Xs[tok][pairpos(dq + i)] = __uint_as_float(f2tf(xa[i]));
            }
        }
        __syncthreads();

        #pragma unroll
        for (int ks = 0; ks < 4; ks++) {
            uint2 aL0 = *(const uint2*)&Ws[wm * 32 + grp     ][ks * 8 + tig * 2];
            uint2 aL1 = *(const uint2*)&Ws[wm * 32 + grp + 8 ][ks * 8 + tig * 2];
            uint2 aH0 = *(const uint2*)&Ws[wm * 32 + grp + 16][ks * 8 + tig * 2];
            uint2 aH1 = *(const uint2*)&Ws[wm * 32 + grp + 24][ks * 8 + tig * 2];
            uint32_t a0[4] = {aL0.x, aL1.x, aL0.y, aL1.y};
            uint32_t a1[4] = {aH0.x, aH1.x, aH0.y, aH1.y};
            #pragma unroll
            for (int nt = 0; nt < 8; nt++) {
                uint2 bb = *(const uint2*)&Xs[wn * 64 + nt * 8 + grp][ks * 8 + tig * 2];
                mma16n8k8(acc[0][nt], a0, bb.x, bb.y);
                mma16n8k8(acc[1][nt], a1, bb.x, bb.y);
            }
        }
    }

    // ---- epilogue ----
    #pragma unroll
    for (int mt = 0; mt < 2; mt++) {
        int r0 = m0 + wm * 32 + mt * 16 + grp;
        int r1 = r0 + 8;
        float bv0 = bias[r0], bv1 = bias[r1];
        #pragma unroll
        for (int nt = 0; nt < 8; nt++) {
            int c = n0 + wn * 64 + nt * 8 + 2 * tig;
            float v00 = acc[mt][nt][0] + bv0, v01 = acc[mt][nt][1] + bv0;
            float v10 = acc[mt][nt][2] + bv1, v11 = acc[mt][nt][3] + bv1;
            if (OUT_MODE == 0) {
                *(float2*)&Y[((size_t)b * E_DIM + r0) * T_DIM + c] = make_float2(v00, v01);
                *(float2*)&Y[((size_t)b * E_DIM + r1) * T_DIM + c] = make_float2(v10, v11);
            } else {
                Y[(((size_t)b * NH + (r0 >> 5)) * T_DIM + c    ) * HD + (r0 & 31)] = v00 * scale;
                Y[(((size_t)b * NH + (r0 >> 5)) * T_DIM + c + 1) * HD + (r0 & 31)] = v01 * scale;
                Y[(((size_t)b * NH + (r1 >> 5)) * T_DIM + c    ) * HD + (r1 & 31)] = v10 * scale;
                Y[(((size_t)b * NH + (r1 >> 5)) * T_DIM + c + 1) * HD + (r1 & 31)] = v11 * scale;
            }
        }
    }
}

// ---------------------------------------------------------------------------
// Warp-MMA (tf32) flash attention, M=32 per warp.
// Block = 128 thr (4 warps), q-tile 128 rows (warp w: rows w*32..+32, 2 m-tiles).
// Key tiles of 64. K/V/P pre-converted to tf32 in smem; paired-k layouts so
// every fragment load is one conflict-free LDS.64.
// ---------------------------------------------------------------------------
__global__ __launch_bounds__(128) void attn_mma_kernel(
    const float* __restrict__ Q, const float* __restrict__ K,
    const float* __restrict__ V, const float* __restrict__ mask,
    float* __restrict__ O)
{
    __shared__ __align__(16) float Ks[64][40];     // [s][k paired]
    __shared__ __align__(16) float Vt[32][72];     // [d][s paired]
    __shared__ __align__(16) float Pp[4][32][72];  // per-warp [q row][s paired]

    const int bh  = blockIdx.y;
    const int q0  = blockIdx.x * 128;
    const int tid = threadIdx.x;
    const int w   = tid >> 5;
    const int l   = tid & 31;
    const int grp = l >> 2;
    const int tig = l & 3;

    // ---- Q fragments (2 m-tiles, held for the whole kernel) ----
    uint32_t qa[2][4][4];
    {
        const float* Qb = Q + ((size_t)bh * T_DIM + q0 + w * 32) * HD;
        #pragma unroll
        for (int mt = 0; mt < 2; mt++)
            #pragma unroll
            for (int ks = 0; ks < 4; ks++) {
                int r0 = mt * 16 + grp, r1 = r0 + 8;
                qa[mt][ks][0] = f2tf(Qb[(size_t)r0 * HD + ks * 8 + tig]);
                qa[mt][ks][1] = f2tf(Qb[(size_t)r1 * HD + ks * 8 + tig]);
                qa[mt][ks][2] = f2tf(Qb[(size_t)r0 * HD + ks * 8 + tig + 4]);
                qa[mt][ks][3] = f2tf(Qb[(size_t)r1 * HD + ks * 8 + tig + 4]);
            }
    }

    float o_[2][4][4];
    #pragma unroll
    for (int mt = 0; mt < 2; mt++)
        #pragma unroll
        for (int nt = 0; nt < 4; nt++)
            #pragma unroll
            for (int j = 0; j < 4; j++) o_[mt][nt][j] = 0.f;

    float m_[4], l_[4];   // state idx r = mt*2 + (0: row grp, 1: row grp+8)
    #pragma unroll
    for (int r = 0; r < 4; r++) { m_[r] = -CUDART_INF_F; l_[r] = 0.f; }

    const float* mr[4];
    #pragma unroll
    for (int r = 0; r < 4; r++)
        mr[r] = mask + (size_t)(q0 + w * 32 + (r >> 1) * 16 + (r & 1) * 8 + grp) * T_DIM;

    const int p0pos = pairpos(2 * tig) & 7;       // position of col 2*tig within 8-block
    const int p1pos = pairpos(2 * tig + 1) & 7;

    for (int s0 = 0; s0 < T_DIM; s0 += 64) {
        __syncthreads();
        // ---- stage K/V tile (tf32-converted, paired layouts) ----
        {
            int s = tid >> 1, h = tid & 1;
            const float4* kg = (const float4*)(K + ((size_t)bh * T_DIM + s0 + s) * HD + h * 16);
            const float4* vg = (const float4*)(V + ((size_t)bh * T_DIM + s0 + s) * HD + h * 16);
            int ps = pairpos(s & 7) | (s & ~7);
            #pragma unroll
            for (int j = 0; j < 4; j++) {
                float4 kv = kg[j];
                float4 vv = vg[j];
                float ka[4] = {kv.x, kv.y, kv.z, kv.w};
                float va[4] = {vv.x, vv.y, vv.z, vv.w};
                #pragma unroll
                for (int i = 0; i < 4; i++) {
                    int d = h * 16 + j * 4 + i;
                    Ks[s][pairpos(d)] = __uint_as_float(f2tf(ka[i]));
                    Vt[d][ps]         = __uint_as_float(f2tf(va[i]));
                }
            }
        }
        __syncthreads();

        // ---- MMA1: S(32x64 per warp) = Q K^T ----
        float sc[2][8][4];
        #pragma unroll
        for (int mt = 0; mt < 2; mt++)
            #pragma unroll
            for (int nt = 0; nt < 8; nt++)
                #pragma unroll
                for (int j = 0; j < 4; j++) sc[mt][nt][j] = 0.f;

        #pragma unroll
        for (int nt = 0; nt < 8; nt++)
            #pragma unroll
            for (int ks = 0; ks < 4; ks++) {
                uint2 bb = *(const uint2*)&Ks[nt * 8 + grp][ks * 8 + tig * 2];
                mma16n8k8(sc[0][nt], qa[0][ks], bb.x, bb.y);
                mma16n8k8(sc[1][nt], qa[1][ks], bb.x, bb.y);
            }

        // ---- + mask (fp32) & row max ----
        float mx[4] = {-CUDART_INF_F, -CUDART_INF_F, -CUDART_INF_F, -CUDART_INF_F};
        #pragma unroll
        for (int mt = 0; mt < 2; mt++)
            #pragma unroll
            for (int nt = 0; nt < 8; nt++) {
                float2 mk0 = __ldg((const float2*)&mr[mt * 2    ][s0 + nt * 8 + 2 * tig]);
                float2 mk1 = __ldg((const float2*)&mr[mt * 2 + 1][s0 + nt * 8 + 2 * tig]);
                sc[mt][nt][0] += mk0.x; sc[mt][nt][1] += mk0.y;
                sc[mt][nt][2] += mk1.x; sc[mt][nt][3] += mk1.y;
                mx[mt * 2]     = fmaxf(mx[mt * 2],     fmaxf(sc[mt][nt][0], sc[mt][nt][1]));
                mx[mt * 2 + 1] = fmaxf(mx[mt * 2 + 1], fmaxf(sc[mt][nt][2], sc[mt][nt][3]));
            }
        #pragma unroll
        for (int r = 0; r < 4; r++) {
            mx[r] = fmaxf(mx[r], __shfl_xor_sync(0xffffffffu, mx[r], 1));
            mx[r] = fmaxf(mx[r], __shfl_xor_sync(0xffffffffu, mx[r], 2));
        }
        float corr[4], sum[4];
        #pragma unroll
        for (int r = 0; r < 4; r++) {
            float mn = fmaxf(m_[r], mx[r]);
            corr[r] = __expf(m_[r] - mn);
            m_[r] = mn;
            sum[r] = 0.f;
        }

        // ---- exp + P store (tf32, paired-k layout) ----
        #pragma unroll
        for (int mt = 0; mt < 2; mt++)
            #pragma unroll
            for (int nt = 0; nt < 8; nt++) {
                float p0 = __expf(sc[mt][nt][0] - m_[mt * 2]);
                float p1 = __expf(sc[mt][nt][1] - m_[mt * 2]);
                float p2 = __expf(sc[mt][nt][2] - m_[mt * 2 + 1]);
                float p3 = __expf(sc[mt][nt][3] - m_[mt * 2 + 1]);
                sum[mt * 2]     += p0 + p1;
                sum[mt * 2 + 1] += p2 + p3;
                Pp[w][mt * 16 + grp    ][nt * 8 + p0pos] = __uint_as_float(f2tf(p0));
                Pp[w][mt * 16 + grp    ][nt * 8 + p1pos] = __uint_as_float(f2tf(p1));
                Pp[w][mt * 16 + grp + 8][nt * 8 + p0pos] = __uint_as_float(f2tf(p2));
                Pp[w][mt * 16 + grp + 8][nt * 8 + p1pos] = __uint_as_float(f2tf(p3));
            }
        #pragma unroll
        for (int r = 0; r < 4; r++) {
            sum[r] += __shfl_xor_sync(0xffffffffu, sum[r], 1);
            sum[r] += __shfl_xor_sync(0xffffffffu, sum[r], 2);
            l_[r] = l_[r] * corr[r] + sum[r];
        }
        #pragma unroll
        for (int mt = 0; mt < 2; mt++)
            #pragma unroll
            for (int nt = 0; nt < 4; nt++) {
                o_[mt][nt][0] *= corr[mt * 2];     o_[mt][nt][1] *= corr[mt * 2];
                o_[mt][nt][2] *= corr[mt * 2 + 1]; o_[mt][nt][3] *= corr[mt * 2 + 1];
            }
        __syncwarp();

        // ---- MMA2: O(32x32) += P(32x64) V(64x32) ----
        #pragma unroll
        for (int ks = 0; ks < 8; ks++) {
            uint2 aL0 = *(const uint2*)&Pp[w][grp     ][ks * 8 + tig * 2];
            uint2 aL1 = *(const uint2*)&Pp[w][grp + 8 ][ks * 8 + tig * 2];
            uint2 aH0 = *(const uint2*)&Pp[w][grp + 16][ks * 8 + tig * 2];
            uint2 aH1 = *(const uint2*)&Pp[w][grp + 24][ks * 8 + tig * 2];
            uint32_t a0[4] = {aL0.x, aL1.x, aL0.y, aL1.y};
            uint32_t a1[4] = {aH0.x, aH1.x, aH0.y, aH1.y};
            #pragma unroll
            for (int nt = 0; nt < 4; nt++) {
                uint2 bb = *(const uint2*)&Vt[nt * 8 + grp][ks * 8 + tig * 2];
                mma16n8k8(o_[0][nt], a0, bb.x, bb.y);
                mma16n8k8(o_[1][nt], a1, bb.x, bb.y);
            }
        }
        __syncwarp();
    }

    // ---- epilogue ----
    #pragma unroll
    for (int mt = 0; mt < 2; mt++) {
        float i0 = 1.f / l_[mt * 2], i1 = 1.f / l_[mt * 2 + 1];
        float* O0 = O + ((size_t)bh * T_DIM + q0 + w * 32 + mt * 16 + grp) * HD;
        float* O1 = O0 + 8 * HD;
        #pragma unroll
        for (int nt = 0; nt < 4; nt++) {
            *(float2*)&O0[nt * 8 + 2 * tig] =
                make_float2(o_[mt][nt][0] * i0, o_[mt][nt][1] * i0);
            *(float2*)&O1[nt * 8 + 2 * tig] =
                make_float2(o_[mt][nt][2] * i1, o_[mt][nt][3] * i1);
        }
    }
}

// ---------------------------------------------------------------------------
extern "C" void kernel_launch(void* const* d_in, const int* in_sizes, int n_in,
                              void* d_out, int out_size)
{
    // metadata order: 0:query 1:key 2:value 3:attn_mask
    //                 4:Wq 5:Wk 6:Wv 7:Wo  8:bq 9:bk 10:bv 11:bo
    const float* query = (const float*)d_in[0];
    const float* key   = (const float*)d_in[1];
    const float* value = (const float*)d_in[2];
    const float* mask  = (const float*)d_in[3];
    const float* Wq    = (const float*)d_in[4];
    const float* Wk    = (const float*)d_in[5];
    const float* Wv    = (const float*)d_in[6];
    const float* Wo    = (const float*)d_in[7];
    const float* bq    = (const float*)d_in[8];
    const float* bk    = (const float*)d_in[9];
    const float* bv    = (const float*)d_in[10];
    const float* bo    = (const float*)d_in[11];
    float* out = (float*)d_out;

    static float *q_buf = nullptr, *k_buf = nullptr, *v_buf = nullptr, *ao_buf = nullptr;
    if (!q_buf) {
        void* p;
        cudaGetSymbolAddress(&p, g_q);  q_buf  = (float*)p;
        cudaGetSymbolAddress(&p, g_k);  k_buf  = (float*)p;
        cudaGetSymbolAddress(&p, g_v);  v_buf  = (float*)p;
        cudaGetSymbolAddress(&p, g_ao); ao_buf = (float*)p;
    }

    const float scale = 0.17677669529663687f;  // 32^-0.5, folded into Q proj

    // QKV projections fused into one launch (grid.z = which*8 + b)
    dim3 gqkv(T_DIM / 256, E_DIM / 64, 3 * B_DIM);
    proj_mma_kernel<0, 1, 1><<<gqkv, 256>>>(
        query, key, value, Wq, Wk, Wv, bq, bk, bv, q_buf, k_buf, v_buf, scale);

    dim3 ag(T_DIM / 128, BHTOT);
    attn_mma_kernel<<<ag, 128>>>(q_buf, k_buf, v_buf, mask, ao_buf);

    dim3 gout(T_DIM / 256, E_DIM / 64, B_DIM);
    proj_mma_kernel<1, 0, 0><<<gout, 256>>>(
        ao_buf, ao_buf, ao_buf, Wo, Wo, Wo, bo, bo, bo, out, out, out, 1.0f);
}

// round 12
// speedup vs baseline: 2.9951x; 1.0489x over previous
#include <cuda_runtime.h>
#include <math_constants.h>
#include <cstdint>

#define E_DIM 256
#define T_DIM 1024
#define NH 8
#define HD 32
#define B_DIM 8
#define BHTOT 64   // B*NH

// Scratch (no allocations allowed): 4 x 8MB fp32
__device__ float g_q [BHTOT * T_DIM * HD];
__device__ float g_k [BHTOT * T_DIM * HD];
__device__ float g_v [BHTOT * T_DIM * HD];
__device__ float g_ao[BHTOT * T_DIM * HD];

// ===========================================================================
// tf32 warp MMA helpers
// ===========================================================================
__device__ __forceinline__ uint32_t f2tf(float x) {
    uint32_t r;
    asm("cvt.rna.tf32.f32 %0, %1;" : "=r"(r) : "f"(x));
    return r;
}

__device__ __forceinline__ void mma16n8k8(float c[4], const uint32_t a[4],
                                          uint32_t b0, uint32_t b1) {
    asm volatile(
        "mma.sync.aligned.m16n8k8.row.col.f32.tf32.tf32.f32 "
        "{%0,%1,%2,%3}, {%4,%5,%6,%7}, {%8,%9}, {%0,%1,%2,%3};"
        : "+f"(c[0]), "+f"(c[1]), "+f"(c[2]), "+f"(c[3])
        : "r"(a[0]), "r"(a[1]), "r"(a[2]), "r"(a[3]), "r"(b0), "r"(b1));
}

// paired-k position: within each aligned 8-block store order (0,4),(1,5),(2,6),(3,7)
__device__ __forceinline__ int pairpos(int k) {
    return (k & ~7) | ((k & 3) << 1) | ((k >> 2) & 1);
}

// ---------------------------------------------------------------------------
// Projection GEMM via tf32 mma: Y = W(E,E) @ X(E,T) + bias (then *scale).
// Block 256 thr (8 warps), tile M=64 x N=256, warp 32x64, K-chunks of 32.
// FUSED=1: blockIdx.z = which*8 + b (QKV in one launch).
// IN_MODE  0: X is [B,E,T]    1: X is [BH,T,HD]
// OUT_MODE 0: Y is [B,E,T]    1: Y is [BH,T,HD] (scaled)
// ---------------------------------------------------------------------------
template<int IN_MODE, int OUT_MODE, int FUSED>
__global__ __launch_bounds__(256) void proj_mma_kernel(
    const float* __restrict__ X0, const float* __restrict__ X1, const float* __restrict__ X2,
    const float* __restrict__ W0, const float* __restrict__ W1, const float* __restrict__ W2,
    const float* __restrict__ c0, const float* __restrict__ c1, const float* __restrict__ c2,
    float* __restrict__ Y0, float* __restrict__ Y1, float* __restrict__ Y2,
    float scale0)
{
    const int zz = blockIdx.z;
    const int b     = FUSED ? (zz & 7) : zz;
    const int which = FUSED ? (zz >> 3) : 0;
    const float* X    = (which == 0) ? X0 : (which == 1) ? X1 : X2;
    const float* Wm   = (which == 0) ? W0 : (which == 1) ? W1 : W2;
    const float* bias = (which == 0) ? c0 : (which == 1) ? c1 : c2;
    float*       Y    = (which == 0) ? Y0 : (which == 1) ? Y1 : Y2;
    const float scale = (which == 0) ? scale0 : 1.0f;

    const int m0 = blockIdx.y * 64;
    const int n0 = blockIdx.x * 256;
    const int tid = threadIdx.x;
    const int w = tid >> 5, l = tid & 31;
    const int wm = w >> 2, wn = w & 3;
    const int grp = l >> 2, tig = l & 3;

    __shared__ __align__(16) float Ws[64][40];    // [m][k paired], tf32 bits
    __shared__ __align__(16) float Xs[256][40];   // [n][k paired], tf32 bits

    float acc[2][8][4];
    #pragma unroll
    for (int mt = 0; mt < 2; mt++)
        #pragma unroll
        for (int nt = 0; nt < 8; nt++)
            #pragma unroll
            for (int j = 0; j < 4; j++) acc[mt][nt][j] = 0.f;

    for (int k0 = 0; k0 < E_DIM; k0 += 32) {
        __syncthreads();
        // ---- stage W tile 64x32 ----
        {
            int m = tid >> 2, kq = (tid & 3) * 8;
            const float4* wg = (const float4*)(Wm + (size_t)(m0 + m) * E_DIM + k0 + kq);
            float4 w0 = wg[0], w1 = wg[1];
            float wa[8] = {w0.x, w0.y, w0.z, w0.w, w1.x, w1.y, w1.z, w1.w};
            #pragma unroll
            for (int i = 0; i < 8; i++)
                Ws[m][pairpos(kq + i)] = __uint_as_float(f2tf(wa[i]));
        }
        // ---- stage X tile 32k x 256n ----
        if (IN_MODE == 0) {
            #pragma unroll
            for (int p = 0; p < 8; p++) {
                int k = (tid >> 6) + p * 4;
                int n = (tid & 63) * 4;
                float4 xv = *(const float4*)&X[((size_t)b * E_DIM + k0 + k) * T_DIM + n0 + n];
                int pc = pairpos(k);
                Xs[n + 0][pc] = __uint_as_float(f2tf(xv.x));
                Xs[n + 1][pc] = __uint_as_float(f2tf(xv.y));
                Xs[n + 2][pc] = __uint_as_float(f2tf(xv.z));
                Xs[n + 3][pc] = __uint_as_float(f2tf(xv.w));
            }
        } else {
            int head = k0 >> 5;
            #pragma unroll
            for (int p = 0; p < 8; p++) {
                int tok = (tid >> 3) + p * 32;
                int dq  = (tid & 7) * 4;
                float4 xv = *(const float4*)&X[(((size_t)b * NH + head) * T_DIM + n0 + tok) * HD + dq];
                float xa[4] = {xv.x, xv.y, xv.z, xv.w};
                #pragma unroll
                for (int i = 0; i < 4; i++)
                    Xs[tok][pairpos(dq + i)] = __uint_as_float(f2tf(xa[i]));
            }
        }
        __syncthreads();

        #pragma unroll
        for (int ks = 0; ks < 4; ks++) {
            uint2 aL0 = *(const uint2*)&Ws[wm * 32 + grp     ][ks * 8 + tig * 2];
            uint2 aL1 = *(const uint2*)&Ws[wm * 32 + grp + 8 ][ks * 8 + tig * 2];
            uint2 aH0 = *(const uint2*)&Ws[wm * 32 + grp + 16][ks * 8 + tig * 2];
            uint2 aH1 = *(const uint2*)&Ws[wm * 32 + grp + 24][ks * 8 + tig * 2];
            uint32_t a0[4] = {aL0.x, aL1.x, aL0.y, aL1.y};
            uint32_t a1[4] = {aH0.x, aH1.x, aH0.y, aH1.y};
            #pragma unroll
            for (int nt = 0; nt < 8; nt++) {
                uint2 bb = *(const uint2*)&Xs[wn * 64 + nt * 8 + grp][ks * 8 + tig * 2];
                mma16n8k8(acc[0][nt], a0, bb.x, bb.y);
                mma16n8k8(acc[1][nt], a1, bb.x, bb.y);
            }
        }
    }

    // ---- epilogue ----
    #pragma unroll
    for (int mt = 0; mt < 2; mt++) {
        int r0 = m0 + wm * 32 + mt * 16 + grp;
        int r1 = r0 + 8;
        float bv0 = bias[r0], bv1 = bias[r1];
        #pragma unroll
        for (int nt = 0; nt < 8; nt++) {
            int c = n0 + wn * 64 + nt * 8 + 2 * tig;
            float v00 = acc[mt][nt][0] + bv0, v01 = acc[mt][nt][1] + bv0;
            float v10 = acc[mt][nt][2] + bv1, v11 = acc[mt][nt][3] + bv1;
            if (OUT_MODE == 0) {
                *(float2*)&Y[((size_t)b * E_DIM + r0) * T_DIM + c] = make_float2(v00, v01);
                *(float2*)&Y[((size_t)b * E_DIM + r1) * T_DIM + c] = make_float2(v10, v11);
            } else {
                Y[(((size_t)b * NH + (r0 >> 5)) * T_DIM + c    ) * HD + (r0 & 31)] = v00 * scale;
                Y[(((size_t)b * NH + (r0 >> 5)) * T_DIM + c + 1) * HD + (r0 & 31)] = v01 * scale;
                Y[(((size_t)b * NH + (r1 >> 5)) * T_DIM + c    ) * HD + (r1 & 31)] = v10 * scale;
                Y[(((size_t)b * NH + (r1 >> 5)) * T_DIM + c + 1) * HD + (r1 & 31)] = v11 * scale;
            }
        }
    }
}

// ---------------------------------------------------------------------------
// Warp-MMA (tf32) flash attention, M=32 per warp.
// Block = 128 thr (4 warps), q-tile 128 rows (warp w: rows w*32..+32, 2 m-tiles).
// Key tiles of 64. K/V/P pre-converted to tf32 in smem; paired-k layouts so
// every fragment load is one conflict-free LDS.64.
// ---------------------------------------------------------------------------
__global__ __launch_bounds__(128) void attn_mma_kernel(
    const float* __restrict__ Q, const float* __restrict__ K,
    const float* __restrict__ V, const float* __restrict__ mask,
    float* __restrict__ O)
{
    __shared__ __align__(16) float Ks[64][40];     // [s][k paired]
    __shared__ __align__(16) float Vt[32][72];     // [d][s paired]
    __shared__ __align__(16) float Pp[4][32][72];  // per-warp [q row][s paired]

    const int bh  = blockIdx.y;
    const int q0  = blockIdx.x * 128;
    const int tid = threadIdx.x;
    const int w   = tid >> 5;
    const int l   = tid & 31;
    const int grp = l >> 2;
    const int tig = l & 3;

    // ---- Q fragments (2 m-tiles, held for the whole kernel) ----
    uint32_t qa[2][4][4];
    {
        const float* Qb = Q + ((size_t)bh * T_DIM + q0 + w * 32) * HD;
        #pragma unroll
        for (int mt = 0; mt < 2; mt++)
            #pragma unroll
            for (int ks = 0; ks < 4; ks++) {
                int r0 = mt * 16 + grp, r1 = r0 + 8;
                qa[mt][ks][0] = f2tf(Qb[(size_t)r0 * HD + ks * 8 + tig]);
                qa[mt][ks][1] = f2tf(Qb[(size_t)r1 * HD + ks * 8 + tig]);
                qa[mt][ks][2] = f2tf(Qb[(size_t)r0 * HD + ks * 8 + tig + 4]);
                qa[mt][ks][3] = f2tf(Qb[(size_t)r1 * HD + ks * 8 + tig + 4]);
            }
    }

    float o_[2][4][4];
    #pragma unroll
    for (int mt = 0; mt < 2; mt++)
        #pragma unroll
        for (int nt = 0; nt < 4; nt++)
            #pragma unroll
            for (int j = 0; j < 4; j++) o_[mt][nt][j] = 0.f;

    float m_[4], l_[4];   // state idx r = mt*2 + (0: row grp, 1: row grp+8)
    #pragma unroll
    for (int r = 0; r < 4; r++) { m_[r] = -CUDART_INF_F; l_[r] = 0.f; }

    const float* mr[4];
    #pragma unroll
    for (int r = 0; r < 4; r++)
        mr[r] = mask + (size_t)(q0 + w * 32 + (r >> 1) * 16 + (r & 1) * 8 + grp) * T_DIM;

    const int p0pos = pairpos(2 * tig) & 7;       // position of col 2*tig within 8-block
    const int p1pos = pairpos(2 * tig + 1) & 7;

    for (int s0 = 0; s0 < T_DIM; s0 += 64) {
        __syncthreads();
        // ---- stage K/V tile (tf32-converted, paired layouts) ----
        {
            int s = tid >> 1, h = tid & 1;
            const float4* kg = (const float4*)(K + ((size_t)bh * T_DIM + s0 + s) * HD + h * 16);
            const float4* vg = (const float4*)(V + ((size_t)bh * T_DIM + s0 + s) * HD + h * 16);
            int ps = pairpos(s & 7) | (s & ~7);
            #pragma unroll
            for (int j = 0; j < 4; j++) {
                float4 kv = kg[j];
                float4 vv = vg[j];
                float ka[4] = {kv.x, kv.y, kv.z, kv.w};
                float va[4] = {vv.x, vv.y, vv.z, vv.w};
                #pragma unroll
                for (int i = 0; i < 4; i++) {
                    int d = h * 16 + j * 4 + i;
                    Ks[s][pairpos(d)] = __uint_as_float(f2tf(ka[i]));
                    Vt[d][ps]         = __uint_as_float(f2tf(va[i]));
                }
            }
        }
        __syncthreads();

        // ---- MMA1: S(32x64 per warp) = Q K^T ----
        float sc[2][8][4];
        #pragma unroll
        for (int mt = 0; mt < 2; mt++)
            #pragma unroll
            for (int nt = 0; nt < 8; nt++)
                #pragma unroll
                for (int j = 0; j < 4; j++) sc[mt][nt][j] = 0.f;

        #pragma unroll
        for (int nt = 0; nt < 8; nt++)
            #pragma unroll
            for (int ks = 0; ks < 4; ks++) {
                uint2 bb = *(const uint2*)&Ks[nt * 8 + grp][ks * 8 + tig * 2];
                mma16n8k8(sc[0][nt], qa[0][ks], bb.x, bb.y);
                mma16n8k8(sc[1][nt], qa[1][ks], bb.x, bb.y);
            }

        // ---- + mask (fp32) & row max ----
        float mx[4] = {-CUDART_INF_F, -CUDART_INF_F, -CUDART_INF_F, -CUDART_INF_F};
        #pragma unroll
        for (int mt = 0; mt < 2; mt++)
            #pragma unroll
            for (int nt = 0; nt < 8; nt++) {
                float2 mk0 = __ldg((const float2*)&mr[mt * 2    ][s0 + nt * 8 + 2 * tig]);
                float2 mk1 = __ldg((const float2*)&mr[mt * 2 + 1][s0 + nt * 8 + 2 * tig]);
                sc[mt][nt][0] += mk0.x; sc[mt][nt][1] += mk0.y;
                sc[mt][nt][2] += mk1.x; sc[mt][nt][3] += mk1.y;
                mx[mt * 2]     = fmaxf(mx[mt * 2],     fmaxf(sc[mt][nt][0], sc[mt][nt][1]));
                mx[mt * 2 + 1] = fmaxf(mx[mt * 2 + 1], fmaxf(sc[mt][nt][2], sc[mt][nt][3]));
            }
        #pragma unroll
        for (int r = 0; r < 4; r++) {
            mx[r] = fmaxf(mx[r], __shfl_xor_sync(0xffffffffu, mx[r], 1));
            mx[r] = fmaxf(mx[r], __shfl_xor_sync(0xffffffffu, mx[r], 2));
        }
        float corr[4], sum[4];
        #pragma unroll
        for (int r = 0; r < 4; r++) {
            float mn = fmaxf(m_[r], mx[r]);
            corr[r] = __expf(m_[r] - mn);
            m_[r] = mn;
            sum[r] = 0.f;
        }

        // ---- exp + P store (tf32, paired-k layout) ----
        #pragma unroll
        for (int mt = 0; mt < 2; mt++)
            #pragma unroll
            for (int nt = 0; nt < 8; nt++) {
                float p0 = __expf(sc[mt][nt][0] - m_[mt * 2]);
                float p1 = __expf(sc[mt][nt][1] - m_[mt * 2]);
                float p2 = __expf(sc[mt][nt][2] - m_[mt * 2 + 1]);
                float p3 = __expf(sc[mt][nt][3] - m_[mt * 2 + 1]);
                sum[mt * 2]     += p0 + p1;
                sum[mt * 2 + 1] += p2 + p3;
                Pp[w][mt * 16 + grp    ][nt * 8 + p0pos] = __uint_as_float(f2tf(p0));
                Pp[w][mt * 16 + grp    ][nt * 8 + p1pos] = __uint_as_float(f2tf(p1));
                Pp[w][mt * 16 + grp + 8][nt * 8 + p0pos] = __uint_as_float(f2tf(p2));
                Pp[w][mt * 16 + grp + 8][nt * 8 + p1pos] = __uint_as_float(f2tf(p3));
            }
        #pragma unroll
        for (int r = 0; r < 4; r++) {
            sum[r] += __shfl_xor_sync(0xffffffffu, sum[r], 1);
            sum[r] += __shfl_xor_sync(0xffffffffu, sum[r], 2);
            l_[r] = l_[r] * corr[r] + sum[r];
        }
        #pragma unroll
        for (int mt = 0; mt < 2; mt++)
            #pragma unroll
            for (int nt = 0; nt < 4; nt++) {
                o_[mt][nt][0] *= corr[mt * 2];     o_[mt][nt][1] *= corr[mt * 2];
                o_[mt][nt][2] *= corr[mt * 2 + 1]; o_[mt][nt][3] *= corr[mt * 2 + 1];
            }
        __syncwarp();

        // ---- MMA2: O(32x32) += P(32x64) V(64x32) ----
        #pragma unroll
        for (int ks = 0; ks < 8; ks++) {
            uint2 aL0 = *(const uint2*)&Pp[w][grp     ][ks * 8 + tig * 2];
            uint2 aL1 = *(const uint2*)&Pp[w][grp + 8 ][ks * 8 + tig * 2];
            uint2 aH0 = *(const uint2*)&Pp[w][grp + 16][ks * 8 + tig * 2];
            uint2 aH1 = *(const uint2*)&Pp[w][grp + 24][ks * 8 + tig * 2];
            uint32_t a0[4] = {aL0.x, aL1.x, aL0.y, aL1.y};
            uint32_t a1[4] = {aH0.x, aH1.x, aH0.y, aH1.y};
            #pragma unroll
            for (int nt = 0; nt < 4; nt++) {
                uint2 bb = *(const uint2*)&Vt[nt * 8 + grp][ks * 8 + tig * 2];
                mma16n8k8(o_[0][nt], a0, bb.x, bb.y);
                mma16n8k8(o_[1][nt], a1, bb.x, bb.y);
            }
        }
        __syncwarp();
    }

    // ---- epilogue ----
    #pragma unroll
    for (int mt = 0; mt < 2; mt++) {
        float i0 = 1.f / l_[mt * 2], i1 = 1.f / l_[mt * 2 + 1];
        float* O0 = O + ((size_t)bh * T_DIM + q0 + w * 32 + mt * 16 + grp) * HD;
        float* O1 = O0 + 8 * HD;
        #pragma unroll
        for (int nt = 0; nt < 4; nt++) {
            *(float2*)&O0[nt * 8 + 2 * tig] =
                make_float2(o_[mt][nt][0] * i0, o_[mt][nt][1] * i0);
            *(float2*)&O1[nt * 8 + 2 * tig] =
                make_float2(o_[mt][nt][2] * i1, o_[mt][nt][3] * i1);
        }
    }
}

// ---------------------------------------------------------------------------
extern "C" void kernel_launch(void* const* d_in, const int* in_sizes, int n_in,
                              void* d_out, int out_size)
{
    // metadata order: 0:query 1:key 2:value 3:attn_mask
    //                 4:Wq 5:Wk 6:Wv 7:Wo  8:bq 9:bk 10:bv 11:bo
    const float* query = (const float*)d_in[0];
    const float* key   = (const float*)d_in[1];
    const float* value = (const float*)d_in[2];
    const float* mask  = (const float*)d_in[3];
    const float* Wq    = (const float*)d_in[4];
    const float* Wk    = (const float*)d_in[5];
    const float* Wv    = (const float*)d_in[6];
    const float* Wo    = (const float*)d_in[7];
    const float* bq    = (const float*)d_in[8];
    const float* bk    = (const float*)d_in[9];
    const float* bv    = (const float*)d_in[10];
    const float* bo    = (const float*)d_in[11];
    float* out = (float*)d_out;

    static float *q_buf = nullptr, *k_buf = nullptr, *v_buf = nullptr, *ao_buf = nullptr;
    if (!q_buf) {
        void* p;
        cudaGetSymbolAddress(&p, g_q);  q_buf  = (float*)p;
        cudaGetSymbolAddress(&p, g_k);  k_buf  = (float*)p;
        cudaGetSymbolAddress(&p, g_v);  v_buf  = (float*)p;
        cudaGetSymbolAddress(&p, g_ao); ao_buf = (float*)p;
    }

    const float scale = 0.17677669529663687f;  // 32^-0.5, folded into Q proj

    // QKV projections fused into one launch (grid.z = which*8 + b)
    dim3 gqkv(T_DIM / 256, E_DIM / 64, 3 * B_DIM);
    proj_mma_kernel<0, 1, 1><<<gqkv, 256>>>(
        query, key, value, Wq, Wk, Wv, bq, bk, bv, q_buf, k_buf, v_buf, scale);

    dim3 ag(T_DIM / 128, BHTOT);
    attn_mma_kernel<<<ag, 128>>>(q_buf, k_buf, v_buf, mask, ao_buf);

    dim3 gout(T_DIM / 256, E_DIM / 64, B_DIM);
    proj_mma_kernel<1, 0, 0><<<gout, 256>>>(
        ao_buf, ao_buf, ao_buf, Wo, Wo, Wo, bo, bo, bo, out, out, out, 1.0f);
}

// round 13
// speedup vs baseline: 3.3180x; 1.1078x over previous
#include <cuda_runtime.h>
#include <math_constants.h>
#include <cstdint>

#define E_DIM 256
#define T_DIM 1024
#define NH 8
#define HD 32
#define B_DIM 8
#define BHTOT 64   // B*NH

// Scratch (no allocations allowed). tf32-bit floats:
//  g_q, g_k : [bh][t][pp(d)]   (channel-paired)
//  g_v      : [bh][d][pp(t)]   (d-major, token-paired)
//  g_ao     : [bh][t][pp(d)]
//  g_xq/k/v : pre-converted inputs, layout unchanged [B,E,T]
__device__ float g_q [BHTOT * T_DIM * HD];
__device__ float g_k [BHTOT * T_DIM * HD];
__device__ float g_v [BHTOT * T_DIM * HD];
__device__ float g_ao[BHTOT * T_DIM * HD];
__device__ float g_xq[B_DIM * E_DIM * T_DIM];
__device__ float g_xk[B_DIM * E_DIM * T_DIM];
__device__ float g_xv[B_DIM * E_DIM * T_DIM];

// ===========================================================================
__device__ __forceinline__ uint32_t f2tf(float x) {
    uint32_t r;
    asm("cvt.rna.tf32.f32 %0, %1;" : "=r"(r) : "f"(x));
    return r;
}
__device__ __forceinline__ float u2f(uint32_t x) { return __uint_as_float(x); }

__device__ __forceinline__ void mma16n8k8(float c[4], const uint32_t a[4],
                                          uint32_t b0, uint32_t b1) {
    asm volatile(
        "mma.sync.aligned.m16n8k8.row.col.f32.tf32.tf32.f32 "
        "{%0,%1,%2,%3}, {%4,%5,%6,%7}, {%8,%9}, {%0,%1,%2,%3};"
        : "+f"(c[0]), "+f"(c[1]), "+f"(c[2]), "+f"(c[3])
        : "r"(a[0]), "r"(a[1]), "r"(a[2]), "r"(a[3]), "r"(b0), "r"(b1));
}

// paired position: within aligned 8-blocks, order (0,4),(1,5),(2,6),(3,7)
__device__ __forceinline__ int pairpos(int k) {
    return (k & ~7) | ((k & 3) << 1) | ((k >> 2) & 1);
}

// ---------------------------------------------------------------------------
// Pre-convert inputs to tf32 bits (once).
// ---------------------------------------------------------------------------
__global__ __launch_bounds__(256) void cvt_kernel(
    const float* __restrict__ a, const float* __restrict__ b,
    const float* __restrict__ c,
    float* __restrict__ oa, float* __restrict__ ob, float* __restrict__ oc)
{
    const float* src = (blockIdx.y == 0) ? a : (blockIdx.y == 1) ? b : c;
    float*       dst = (blockIdx.y == 0) ? oa : (blockIdx.y == 1) ? ob : oc;
    size_t i = ((size_t)blockIdx.x * 256 + threadIdx.x) * 4;
    float4 v = *(const float4*)(src + i);
    v.x = u2f(f2tf(v.x)); v.y = u2f(f2tf(v.y));
    v.z = u2f(f2tf(v.z)); v.w = u2f(f2tf(v.w));
    *(float4*)(dst + i) = v;
}

// ---------------------------------------------------------------------------
// Projection GEMM via tf32 mma, B-operand DIRECT from gmem (no X smem).
// Block 256 thr (8 warps: 2m x 4n), tile M=64 x N=256, warp 32x64, K-chunk 32.
// IN_MODE 0: X tf32-bits [B,E,T] (2x LDG.32 per frag)
// IN_MODE 1: X tf32-paired [BH,T,HD] (1x LDG.64 per frag)
// OUT_MODE 0: Y fp32 [B,E,T]
// OUT_MODE 1: which<2 -> paired [BH,T,pp(d)] (*scale for which==0)
//             which==2 -> transposed paired [BH,HD,pp(t)]  (V)
// ---------------------------------------------------------------------------
template<int IN_MODE, int OUT_MODE, int FUSED>
__global__ __launch_bounds__(256) void proj_mma_kernel(
    const float* __restrict__ X0, const float* __restrict__ X1, const float* __restrict__ X2,
    const float* __restrict__ W0, const float* __restrict__ W1, const float* __restrict__ W2,
    const float* __restrict__ c0, const float* __restrict__ c1, const float* __restrict__ c2,
    float* __restrict__ Y0, float* __restrict__ Y1, float* __restrict__ Y2,
    float scale0)
{
    const int zz = blockIdx.z;
    const int b     = FUSED ? (zz & 7) : zz;
    const int which = FUSED ? (zz >> 3) : 0;
    const float* X    = (which == 0) ? X0 : (which == 1) ? X1 : X2;
    const float* Wm   = (which == 0) ? W0 : (which == 1) ? W1 : W2;
    const float* bias = (which == 0) ? c0 : (which == 1) ? c1 : c2;
    float*       Y    = (which == 0) ? Y0 : (which == 1) ? Y1 : Y2;
    const float scale = (which == 0) ? scale0 : 1.0f;

    const int m0 = blockIdx.y * 64;
    const int n0 = blockIdx.x * 256;
    const int tid = threadIdx.x;
    const int w = tid >> 5, l = tid & 31;
    const int wm = w >> 2, wn = w & 3;
    const int grp = l >> 2, tig = l & 3;

    __shared__ __align__(16) float Ws[64][40];   // [m][k paired], tf32 bits

    float acc[2][8][4];
    #pragma unroll
    for (int mt = 0; mt < 2; mt++)
        #pragma unroll
        for (int nt = 0; nt < 8; nt++)
            #pragma unroll
            for (int j = 0; j < 4; j++) acc[mt][nt][j] = 0.f;

    for (int k0 = 0; k0 < E_DIM; k0 += 32) {
        __syncthreads();
        // ---- stage W tile 64x32 (tf32, paired) ----
        {
            int m = tid >> 2, kq = (tid & 3) * 8;
            const float4* wg = (const float4*)(Wm + (size_t)(m0 + m) * E_DIM + k0 + kq);
            float4 w0 = wg[0], w1 = wg[1];
            float wa[8] = {w0.x, w0.y, w0.z, w0.w, w1.x, w1.y, w1.z, w1.w};
            #pragma unroll
            for (int i = 0; i < 8; i++)
                Ws[m][pairpos(kq + i)] = u2f(f2tf(wa[i]));
        }
        __syncthreads();

        const float* xb  = X + ((size_t)b * E_DIM + k0) * T_DIM + n0 + wn * 64 + grp;
        const float* xb1 = X + (((size_t)b * NH + (k0 >> 5)) * T_DIM + n0 + wn * 64 + grp) * HD;

        #pragma unroll
        for (int ks = 0; ks < 4; ks++) {
            uint2 aL0 = *(const uint2*)&Ws[wm * 32 + grp     ][ks * 8 + tig * 2];
            uint2 aL1 = *(const uint2*)&Ws[wm * 32 + grp + 8 ][ks * 8 + tig * 2];
            uint2 aH0 = *(const uint2*)&Ws[wm * 32 + grp + 16][ks * 8 + tig * 2];
            uint2 aH1 = *(const uint2*)&Ws[wm * 32 + grp + 24][ks * 8 + tig * 2];
            uint32_t a0[4] = {aL0.x, aL1.x, aL0.y, aL1.y};
            uint32_t a1[4] = {aH0.x, aH1.x, aH0.y, aH1.y};
            #pragma unroll
            for (int nt = 0; nt < 8; nt++) {
                uint32_t b0, b1;
                if (IN_MODE == 0) {
                    b0 = __float_as_uint(__ldg(xb + (size_t)(ks * 8 + tig    ) * T_DIM + nt * 8));
                    b1 = __float_as_uint(__ldg(xb + (size_t)(ks * 8 + tig + 4) * T_DIM + nt * 8));
                } else {
                    uint2 bb = *(const uint2*)(xb1 + (size_t)nt * 8 * HD + ks * 8 + 2 * tig);
                    b0 = bb.x; b1 = bb.y;
                }
                mma16n8k8(acc[0][nt], a0, b0, b1);
                mma16n8k8(acc[1][nt], a1, b0, b1);
            }
        }
    }

    // ---- epilogue ----
    const int head = (m0 + wm * 32) >> 5;
    #pragma unroll
    for (int mt = 0; mt < 2; mt++) {
        int r0 = m0 + wm * 32 + mt * 16 + grp;
        int r1 = r0 + 8;
        float bv0 = bias[r0], bv1 = bias[r1];
        #pragma unroll
        for (int nt = 0; nt < 8; nt++) {
            int c = n0 + wn * 64 + nt * 8 + 2 * tig;
            float v00 = (acc[mt][nt][0] + bv0) * scale;
            float v01 = (acc[mt][nt][1] + bv0) * scale;
            float v10 = (acc[mt][nt][2] + bv1) * scale;
            float v11 = (acc[mt][nt][3] + bv1) * scale;
            if (OUT_MODE == 0) {
                *(float2*)&Y[((size_t)b * E_DIM + r0) * T_DIM + c] = make_float2(v00, v01);
                *(float2*)&Y[((size_t)b * E_DIM + r1) * T_DIM + c] = make_float2(v10, v11);
            } else {
                uint32_t t00 = f2tf(v00), t01 = f2tf(v01);
                uint32_t t10 = f2tf(v10), t11 = f2tf(v11);
                if (which != 2) {
                    // pair channels (d, d+4): partner lane = l ^ 16
                    uint32_t u00 = __shfl_xor_sync(0xffffffffu, t00, 16);
                    uint32_t u01 = __shfl_xor_sync(0xffffffffu, t01, 16);
                    uint32_t u10 = __shfl_xor_sync(0xffffffffu, t10, 16);
                    uint32_t u11 = __shfl_xor_sync(0xffffffffu, t11, 16);
                    if (l < 16) {
                        float* y0 = Y + (((size_t)b * NH + head) * T_DIM + c) * HD;
                        float* y1 = y0 + HD;
                        int o0 = mt * 16 + 2 * grp;
                        int o1 = o0 + 8;
                        *(float2*)&y0[o0] = make_float2(u2f(t00), u2f(u00));
                        *(float2*)&y1[o0] = make_float2(u2f(t01), u2f(u01));
                        *(float2*)&y0[o1] = make_float2(u2f(t10), u2f(u10));
                        *(float2*)&y1[o1] = make_float2(u2f(t11), u2f(u11));
                    }
                } else {
                    // V: pair tokens (t, t+4): partner lane = l ^ 2
                    uint32_t u00 = __shfl_xor_sync(0xffffffffu, t00, 2);
                    uint32_t u01 = __shfl_xor_sync(0xffffffffu, t01, 2);
                    uint32_t u10 = __shfl_xor_sync(0xffffffffu, t10, 2);
                    uint32_t u11 = __shfl_xor_sync(0xffffffffu, t11, 2);
                    if (tig < 2) {
                        int d0 = mt * 16 + grp, d1 = d0 + 8;
                        int cb = n0 + wn * 64 + nt * 8 + 4 * tig;
                        float* z0 = Y + (((size_t)b * NH + head) * HD + d0) * T_DIM + cb;
                        float* z1 = Y + (((size_t)b * NH + head) * HD + d1) * T_DIM + cb;
                        *(float4*)z0 = make_float4(u2f(t00), u2f(u00), u2f(t01), u2f(u01));
                        *(float4*)z1 = make_float4(u2f(t10), u2f(u10), u2f(t11), u2f(u11));
                    }
                }
            }
        }
    }
}

// ---------------------------------------------------------------------------
// Warp-MMA (tf32) flash attention. Buffers are tf32-bit fragment-layouts:
// Q [bh][t][pp(d)], K [bh][t][pp(d)], V [bh][d][pp(t)] -> staging = pure copies.
// Block 128 thr (4 warps), q-tile 128 (warp: 32 q), key tiles of 64.
// ---------------------------------------------------------------------------
__global__ __launch_bounds__(128) void attn_mma_kernel(
    const float* __restrict__ Q, const float* __restrict__ K,
    const float* __restrict__ V, const float* __restrict__ mask,
    float* __restrict__ O)
{
    __shared__ __align__(16) float Ks[64][40];     // [s][k paired]
    __shared__ __align__(16) float Vt[32][72];     // [d][s paired]
    __shared__ __align__(16) float Pp[4][32][72];  // per-warp P [q][s paired]

    const int bh  = blockIdx.y;
    const int q0  = blockIdx.x * 128;
    const int tid = threadIdx.x;
    const int w   = tid >> 5;
    const int l   = tid & 31;
    const int grp = l >> 2;
    const int tig = l & 3;

    // ---- Q fragments: direct paired loads, no cvt ----
    uint32_t qa[2][4][4];
    {
        const float* Qb = Q + ((size_t)bh * T_DIM + q0 + w * 32) * HD;
        #pragma unroll
        for (int mt = 0; mt < 2; mt++)
            #pragma unroll
            for (int ks = 0; ks < 4; ks++) {
                uint2 p0 = *(const uint2*)(Qb + (size_t)(mt * 16 + grp    ) * HD + ks * 8 + 2 * tig);
                uint2 p1 = *(const uint2*)(Qb + (size_t)(mt * 16 + grp + 8) * HD + ks * 8 + 2 * tig);
                qa[mt][ks][0] = p0.x; qa[mt][ks][1] = p1.x;
                qa[mt][ks][2] = p0.y; qa[mt][ks][3] = p1.y;
            }
    }

    float o_[2][4][4];
    #pragma unroll
    for (int mt = 0; mt < 2; mt++)
        #pragma unroll
        for (int nt = 0; nt < 4; nt++)
            #pragma unroll
            for (int j = 0; j < 4; j++) o_[mt][nt][j] = 0.f;

    float m_[4], l_[4];
    #pragma unroll
    for (int r = 0; r < 4; r++) { m_[r] = -CUDART_INF_F; l_[r] = 0.f; }

    const float* mr[4];
    #pragma unroll
    for (int r = 0; r < 4; r++)
        mr[r] = mask + (size_t)(q0 + w * 32 + (r >> 1) * 16 + (r & 1) * 8 + grp) * T_DIM;

    const int p0pos = pairpos(2 * tig) & 7;
    const int p1pos = pairpos(2 * tig + 1) & 7;

    for (int s0 = 0; s0 < T_DIM; s0 += 64) {
        __syncthreads();
        // ---- stage K tile: straight copy (already tf32-paired) ----
        {
            int s = tid >> 1, h = (tid & 1) * 16;
            const float4* kg = (const float4*)(K + ((size_t)bh * T_DIM + s0 + s) * HD + h);
            float4* kd = (float4*)&Ks[s][h];
            kd[0] = kg[0]; kd[1] = kg[1]; kd[2] = kg[2]; kd[3] = kg[3];
        }
        // ---- stage V tile: straight copy (d-major, token-paired) ----
        {
            int d = tid >> 2, seg = (tid & 3) * 16;
            const float4* vg = (const float4*)(V + ((size_t)bh * HD + d) * T_DIM + s0 + seg);
            float4* vd = (float4*)&Vt[d][seg];
            vd[0] = vg[0]; vd[1] = vg[1]; vd[2] = vg[2]; vd[3] = vg[3];
        }
        __syncthreads();

        // ---- MMA1: S(32x64 per warp) = Q K^T ----
        float sc[2][8][4];
        #pragma unroll
        for (int mt = 0; mt < 2; mt++)
            #pragma unroll
            for (int nt = 0; nt < 8; nt++)
                #pragma unroll
                for (int j = 0; j < 4; j++) sc[mt][nt][j] = 0.f;

        #pragma unroll
        for (int nt = 0; nt < 8; nt++)
            #pragma unroll
            for (int ks = 0; ks < 4; ks++) {
                uint2 bb = *(const uint2*)&Ks[nt * 8 + grp][ks * 8 + tig * 2];
                mma16n8k8(sc[0][nt], qa[0][ks], bb.x, bb.y);
                mma16n8k8(sc[1][nt], qa[1][ks], bb.x, bb.y);
            }

        // ---- + mask (fp32) & row max ----
        float mx[4] = {-CUDART_INF_F, -CUDART_INF_F, -CUDART_INF_F, -CUDART_INF_F};
        #pragma unroll
        for (int mt = 0; mt < 2; mt++)
            #pragma unroll
            for (int nt = 0; nt < 8; nt++) {
                float2 mk0 = __ldg((const float2*)&mr[mt * 2    ][s0 + nt * 8 + 2 * tig]);
                float2 mk1 = __ldg((const float2*)&mr[mt * 2 + 1][s0 + nt * 8 + 2 * tig]);
                sc[mt][nt][0] += mk0.x; sc[mt][nt][1] += mk0.y;
                sc[mt][nt][2] += mk1.x; sc[mt][nt][3] += mk1.y;
                mx[mt * 2]     = fmaxf(mx[mt * 2],     fmaxf(sc[mt][nt][0], sc[mt][nt][1]));
                mx[mt * 2 + 1] = fmaxf(mx[mt * 2 + 1], fmaxf(sc[mt][nt][2], sc[mt][nt][3]));
            }
        #pragma unroll
        for (int r = 0; r < 4; r++) {
            mx[r] = fmaxf(mx[r], __shfl_xor_sync(0xffffffffu, mx[r], 1));
            mx[r] = fmaxf(mx[r], __shfl_xor_sync(0xffffffffu, mx[r], 2));
        }
        float corr[4], sum[4];
        #pragma unroll
        for (int r = 0; r < 4; r++) {
            float mn = fmaxf(m_[r], mx[r]);
            corr[r] = __expf(m_[r] - mn);
            m_[r] = mn;
            sum[r] = 0.f;
        }

        // ---- exp + P store (tf32, paired layout) ----
        #pragma unroll
        for (int mt = 0; mt < 2; mt++)
            #pragma unroll
            for (int nt = 0; nt < 8; nt++) {
                float p0 = __expf(sc[mt][nt][0] - m_[mt * 2]);
                float p1 = __expf(sc[mt][nt][1] - m_[mt * 2]);
                float p2 = __expf(sc[mt][nt][2] - m_[mt * 2 + 1]);
                float p3 = __expf(sc[mt][nt][3] - m_[mt * 2 + 1]);
                sum[mt * 2]     += p0 + p1;
                sum[mt * 2 + 1] += p2 + p3;
                Pp[w][mt * 16 + grp    ][nt * 8 + p0pos] = u2f(f2tf(p0));
                Pp[w][mt * 16 + grp    ][nt * 8 + p1pos] = u2f(f2tf(p1));
                Pp[w][mt * 16 + grp + 8][nt * 8 + p0pos] = u2f(f2tf(p2));
                Pp[w][mt * 16 + grp + 8][nt * 8 + p1pos] = u2f(f2tf(p3));
            }
        #pragma unroll
        for (int r = 0; r < 4; r++) {
            sum[r] += __shfl_xor_sync(0xffffffffu, sum[r], 1);
            sum[r] += __shfl_xor_sync(0xffffffffu, sum[r], 2);
            l_[r] = l_[r] * corr[r] + sum[r];
        }
        #pragma unroll
        for (int mt = 0; mt < 2; mt++)
            #pragma unroll
            for (int nt = 0; nt < 4; nt++) {
                o_[mt][nt][0] *= corr[mt * 2];     o_[mt][nt][1] *= corr[mt * 2];
                o_[mt][nt][2] *= corr[mt * 2 + 1]; o_[mt][nt][3] *= corr[mt * 2 + 1];
            }
        __syncwarp();

        // ---- MMA2: O(32x32) += P(32x64) V(64x32) ----
        #pragma unroll
        for (int ks = 0; ks < 8; ks++) {
            uint2 aL0 = *(const uint2*)&Pp[w][grp     ][ks * 8 + tig * 2];
            uint2 aL1 = *(const uint2*)&Pp[w][grp + 8 ][ks * 8 + tig * 2];
            uint2 aH0 = *(const uint2*)&Pp[w][grp + 16][ks * 8 + tig * 2];
            uint2 aH1 = *(const uint2*)&Pp[w][grp + 24][ks * 8 + tig * 2];
            uint32_t a0[4] = {aL0.x, aL1.x, aL0.y, aL1.y};
            uint32_t a1[4] = {aH0.x, aH1.x, aH0.y, aH1.y};
            #pragma unroll
            for (int nt = 0; nt < 4; nt++) {
                uint2 bb = *(const uint2*)&Vt[nt * 8 + grp][ks * 8 + tig * 2];
                mma16n8k8(o_[0][nt], a0, bb.x, bb.y);
                mma16n8k8(o_[1][nt], a1, bb.x, bb.y);
            }
        }
        __syncwarp();
    }

    // ---- epilogue: write ao as tf32-paired [bh][t][pp(d)] ----
    #pragma unroll
    for (int mt = 0; mt < 2; mt++) {
        float i0 = 1.f / l_[mt * 2], i1 = 1.f / l_[mt * 2 + 1];
        #pragma unroll
        for (int nt = 0; nt < 4; nt++) {
            uint32_t t0 = f2tf(o_[mt][nt][0] * i0), t1 = f2tf(o_[mt][nt][1] * i0);
            uint32_t t2 = f2tf(o_[mt][nt][2] * i1), t3 = f2tf(o_[mt][nt][3] * i1);
            uint32_t u0 = __shfl_xor_sync(0xffffffffu, t0, 2);
            uint32_t u1 = __shfl_xor_sync(0xffffffffu, t1, 2);
            uint32_t u2 = __shfl_xor_sync(0xffffffffu, t2, 2);
            uint32_t u3 = __shfl_xor_sync(0xffffffffu, t3, 2);
            if (tig < 2) {
                size_t r0 = (size_t)bh * T_DIM + q0 + w * 32 + mt * 16 + grp;
                float* z0 = O + r0 * HD + nt * 8 + 4 * tig;
                float* z1 = z0 + 8 * HD;
                *(float4*)z0 = make_float4(u2f(t0), u2f(u0), u2f(t1), u2f(u1));
                *(float4*)z1 = make_float4(u2f(t2), u2f(u2), u2f(t3), u2f(u3));
            }
        }
    }
}

// ---------------------------------------------------------------------------
extern "C" void kernel_launch(void* const* d_in, const int* in_sizes, int n_in,
                              void* d_out, int out_size)
{
    // metadata order: 0:query 1:key 2:value 3:attn_mask
    //                 4:Wq 5:Wk 6:Wv 7:Wo  8:bq 9:bk 10:bv 11:bo
    const float* query = (const float*)d_in[0];
    const float* key   = (const float*)d_in[1];
    const float* value = (const float*)d_in[2];
    const float* mask  = (const float*)d_in[3];
    const float* Wq    = (const float*)d_in[4];
    const float* Wk    = (const float*)d_in[5];
    const float* Wv    = (const float*)d_in[6];
    const float* Wo    = (const float*)d_in[7];
    const float* bq    = (const float*)d_in[8];
    const float* bk    = (const float*)d_in[9];
    const float* bv    = (const float*)d_in[10];
    const float* bo    = (const float*)d_in[11];
    float* out = (float*)d_out;

    static float *q_buf = nullptr, *k_buf, *v_buf, *ao_buf, *xq, *xk, *xv;
    if (!q_buf) {
        void* p;
        cudaGetSymbolAddress(&p, g_q);  q_buf  = (float*)p;
        cudaGetSymbolAddress(&p, g_k);  k_buf  = (float*)p;
        cudaGetSymbolAddress(&p, g_v);  v_buf  = (float*)p;
        cudaGetSymbolAddress(&p, g_ao); ao_buf = (float*)p;
        cudaGetSymbolAddress(&p, g_xq); xq = (float*)p;
        cudaGetSymbolAddress(&p, g_xk); xk = (float*)p;
        cudaGetSymbolAddress(&p, g_xv); xv = (float*)p;
    }

    const float scale = 0.17677669529663687f;  // 32^-0.5, folded into Q proj

    // 1) pre-convert inputs to tf32 bits
    dim3 gc(B_DIM * E_DIM * T_DIM / (256 * 4), 3);
    cvt_kernel<<<gc, 256>>>(query, key, value, xq, xk, xv);

    // 2) QKV projections fused (grid.z = which*8 + b)
    dim3 gqkv(T_DIM / 256, E_DIM / 64, 3 * B_DIM);
    proj_mma_kernel<0, 1, 1><<<gqkv, 256>>>(
        xq, xk, xv, Wq, Wk, Wv, bq, bk, bv, q_buf, k_buf, v_buf, scale);

    // 3) attention
    dim3 ag(T_DIM / 128, BHTOT);
    attn_mma_kernel<<<ag, 128>>>(q_buf, k_buf, v_buf, mask, ao_buf);

    // 4) output projection (direct paired B-frags from ao)
    dim3 gout(T_DIM / 256, E_DIM / 64, B_DIM);
    proj_mma_kernel<1, 0, 0><<<gout, 256>>>(
        ao_buf, ao_buf, ao_buf, Wo, Wo, Wo, bo, bo, bo, out, out, out, 1.0f);
}

// round 14
// speedup vs baseline: 4.5562x; 1.3732x over previous
#include <cuda_runtime.h>
#include <math_constants.h>
#include <cstdint>

#define E_DIM 256
#define T_DIM 1024
#define NH 8
#define HD 32
#define B_DIM 8
#define BHTOT 64   // B*NH

// Scratch (no allocations allowed). tf32-bit floats:
//  g_q, g_k : [bh][t][pp(d)]       g_v : [bh][d][pp(t)]      g_ao : [bh][t][pp(d)]
//  g_xt     : [tensor][b][t][pp(e)]  (transposed, paired, tf32)
//  g_wp     : [4][m][pp(k)]          (paired tf32 weights q,k,v,o)
__device__ float g_q [BHTOT * T_DIM * HD];
__device__ float g_k [BHTOT * T_DIM * HD];
__device__ float g_v [BHTOT * T_DIM * HD];
__device__ float g_ao[BHTOT * T_DIM * HD];
__device__ float g_xt[3u * B_DIM * T_DIM * E_DIM];
__device__ float g_wp[4 * E_DIM * E_DIM];

// ===========================================================================
__device__ __forceinline__ uint32_t f2tf(float x) {
    uint32_t r;
    asm("cvt.rna.tf32.f32 %0, %1;" : "=r"(r) : "f"(x));
    return r;
}
__device__ __forceinline__ float u2f(uint32_t x) { return __uint_as_float(x); }

__device__ __forceinline__ void mma16n8k8(float c[4], const uint32_t a[4],
                                          uint32_t b0, uint32_t b1) {
    asm volatile(
        "mma.sync.aligned.m16n8k8.row.col.f32.tf32.tf32.f32 "
        "{%0,%1,%2,%3}, {%4,%5,%6,%7}, {%8,%9}, {%0,%1,%2,%3};"
        : "+f"(c[0]), "+f"(c[1]), "+f"(c[2]), "+f"(c[3])
        : "r"(a[0]), "r"(a[1]), "r"(a[2]), "r"(a[3]), "r"(b0), "r"(b1));
}

// paired position: within aligned 8-blocks, order (0,4),(1,5),(2,6),(3,7)
__device__ __forceinline__ int pairpos(int k) {
    return (k & ~7) | ((k & 3) << 1) | ((k >> 2) & 1);
}
// inverse: source k for paired position p
__device__ __forceinline__ int srck(int p) {
    return (p & ~7) | ((p & 7) >> 1) | ((p & 1) << 2);
}

__device__ __forceinline__ uint32_t smem_u32(const void* p) {
    uint32_t a;
    asm("{ .reg .u64 t; cvta.to.shared.u64 t, %1; cvt.u32.u64 %0, t; }" : "=r"(a) : "l"(p));
    return a;
}
__device__ __forceinline__ void cp_async16(uint32_t dst, const void* src) {
    asm volatile("cp.async.ca.shared.global [%0], [%1], 16;" :: "r"(dst), "l"(src));
}
#define CP_COMMIT() asm volatile("cp.async.commit_group;" ::: "memory")
#define CP_WAIT0()  asm volatile("cp.async.wait_group 0;" ::: "memory")
#define CP_WAIT1()  asm volatile("cp.async.wait_group 1;" ::: "memory")

// ---------------------------------------------------------------------------
// Weight pre-convert: W[m][k] fp32 -> g_wp[wi][m][pp(k)] tf32 bits.
// ---------------------------------------------------------------------------
__global__ void wcvt_kernel(const float* __restrict__ Wq, const float* __restrict__ Wk,
                            const float* __restrict__ Wv, const float* __restrict__ Wo,
                            float* __restrict__ out)
{
    const float* W = (blockIdx.y == 0) ? Wq : (blockIdx.y == 1) ? Wk
                   : (blockIdx.y == 2) ? Wv : Wo;
    int m = blockIdx.x;
    int p = threadIdx.x * 4;
    const float* row = W + (size_t)m * E_DIM;
    float4 v;
    v.x = u2f(f2tf(row[srck(p + 0)]));
    v.y = u2f(f2tf(row[srck(p + 1)]));
    v.z = u2f(f2tf(row[srck(p + 2)]));
    v.w = u2f(f2tf(row[srck(p + 3)]));
    *(float4*)(out + ((size_t)blockIdx.y * E_DIM + m) * E_DIM + p) = v;
}

// ---------------------------------------------------------------------------
// Input transpose+convert: X[b][e][t] fp32 -> g_xt[tensor][b][t][pp(e)] tf32.
// Block 256, tile 64e x 64t, smem transpose.
// ---------------------------------------------------------------------------
__global__ __launch_bounds__(256) void xt_kernel(
    const float* __restrict__ q, const float* __restrict__ k,
    const float* __restrict__ v, float* __restrict__ out)
{
    __shared__ float Ts[64][65];
    const int tz = blockIdx.z;
    const int tensor = tz >> 3, b = tz & 7;
    const float* X = (tensor == 0) ? q : (tensor == 1) ? k : v;
    const int e0 = blockIdx.y * 64, t0 = blockIdx.x * 64;
    const int tid = threadIdx.x;

    #pragma unroll
    for (int j = 0; j < 4; j++) {
        int e  = (tid >> 4) + j * 16;
        int t4 = (tid & 15) * 4;
        float4 val = *(const float4*)&X[((size_t)b * E_DIM + e0 + e) * T_DIM + t0 + t4];
        Ts[e][t4 + 0] = val.x; Ts[e][t4 + 1] = val.y;
        Ts[e][t4 + 2] = val.z; Ts[e][t4 + 3] = val.w;
    }
    __syncthreads();
    float* ob = out + (size_t)tensor * (B_DIM * T_DIM * E_DIM)
              + ((size_t)b * T_DIM + t0) * E_DIM + e0;
    #pragma unroll
    for (int j = 0; j < 8; j++) {
        int t = (tid >> 5) + j * 8;
        int e = tid & 31;
        ob[(size_t)t * E_DIM + pairpos(e)]      = u2f(f2tf(Ts[e][t]));
        ob[(size_t)t * E_DIM + pairpos(e + 32)] = u2f(f2tf(Ts[e + 32][t]));
    }
}

// ---------------------------------------------------------------------------
// QKV projection, cp.async double-buffered, all-tf32-paired operands.
// Block 256 (8 warps: 2m x 4n), tile M=64 x N=256, K-chunk 32, 8 chunks.
// Dynamic smem: Xs[2][256][40] + Ws[2][64][40] = 102400 B.
// grid (4, 4, 24: which*8+b). Outputs q/k paired [bh][t][pp(d)], v [bh][d][pp(t)].
// ---------------------------------------------------------------------------
#define QKV_STAGE(KK0, BUF) do {                                               \
    _Pragma("unroll")                                                          \
    for (int j = 0; j < 8; j++) {                                              \
        int r = (tid >> 3) + j * 32;                                           \
        int seg = tid & 7;                                                     \
        cp_async16(xs_a + (((BUF) * 256 + r) * 40 + seg * 4) * 4,              \
                   Xb + (size_t)(n0 + r) * E_DIM + (KK0) + seg * 4);           \
    }                                                                          \
    _Pragma("unroll")                                                          \
    for (int j = 0; j < 2; j++) {                                              \
        int r = (tid >> 3) + j * 32;                                           \
        int seg = tid & 7;                                                     \
        cp_async16(ws_a + (((BUF) * 64 + r) * 40 + seg * 4) * 4,               \
                   Wm + (size_t)(m0 + r) * E_DIM + (KK0) + seg * 4);           \
    }                                                                          \
    CP_COMMIT();                                                               \
} while (0)

__global__ __launch_bounds__(256) void proj_qkv_kernel(
    const float* __restrict__ Xt, const float* __restrict__ Wp,
    const float* __restrict__ bq, const float* __restrict__ bk,
    const float* __restrict__ bv,
    float* __restrict__ Yq, float* __restrict__ Yk, float* __restrict__ Yv,
    float scale0)
{
    extern __shared__ float sm[];
    float* Xs  = sm;                 // [2][256][40]
    float* Wsm = sm + 2 * 256 * 40;  // [2][64][40]

    const int zz = blockIdx.z;
    const int b = zz & 7, which = zz >> 3;
    const float* Xb = Xt + (((size_t)which * B_DIM + b) * T_DIM) * E_DIM;
    const float* Wm = Wp + (size_t)which * E_DIM * E_DIM;
    const float* bias = (which == 0) ? bq : (which == 1) ? bk : bv;
    float* Y = (which == 0) ? Yq : (which == 1) ? Yk : Yv;
    const float scale = (which == 0) ? scale0 : 1.0f;

    const int m0 = blockIdx.y * 64;
    const int n0 = blockIdx.x * 256;
    const int tid = threadIdx.x;
    const int w = tid >> 5, l = tid & 31;
    const int wm = w >> 2, wn = w & 3;
    const int grp = l >> 2, tig = l & 3;

    const uint32_t xs_a = smem_u32(Xs);
    const uint32_t ws_a = smem_u32(Wsm);

    float acc[2][8][4];
    #pragma unroll
    for (int mt = 0; mt < 2; mt++)
        #pragma unroll
        for (int nt = 0; nt < 8; nt++)
            #pragma unroll
            for (int j = 0; j < 4; j++) acc[mt][nt][j] = 0.f;

    QKV_STAGE(0, 0);

    for (int c = 0; c < 8; c++) {
        const int buf = c & 1;
        if (c < 7) { QKV_STAGE((c + 1) * 32, buf ^ 1); CP_WAIT1(); }
        else       { CP_WAIT0(); }
        __syncthreads();

        #pragma unroll
        for (int ks = 0; ks < 4; ks++) {
            const float* wrow = &Wsm[(buf * 64 + wm * 32 + grp) * 40 + ks * 8 + tig * 2];
            uint2 aL0 = *(const uint2*)(wrow);
            uint2 aL1 = *(const uint2*)(wrow + 8 * 40);
            uint2 aH0 = *(const uint2*)(wrow + 16 * 40);
            uint2 aH1 = *(const uint2*)(wrow + 24 * 40);
            uint32_t a0[4] = {aL0.x, aL1.x, aL0.y, aL1.y};
            uint32_t a1[4] = {aH0.x, aH1.x, aH0.y, aH1.y};
            #pragma unroll
            for (int nt = 0; nt < 8; nt++) {
                uint2 bb = *(const uint2*)&Xs[(buf * 256 + wn * 64 + nt * 8 + grp) * 40
                                              + ks * 8 + tig * 2];
                mma16n8k8(acc[0][nt], a0, bb.x, bb.y);
                mma16n8k8(acc[1][nt], a1, bb.x, bb.y);
            }
        }
        __syncthreads();
    }

    // ---- epilogue (tf32-paired outputs) ----
    const int head = (m0 + wm * 32) >> 5;
    #pragma unroll
    for (int mt = 0; mt < 2; mt++) {
        int r0 = m0 + wm * 32 + mt * 16 + grp;
        int r1 = r0 + 8;
        float bv0 = bias[r0], bv1 = bias[r1];
        #pragma unroll
        for (int nt = 0; nt < 8; nt++) {
            int c = n0 + wn * 64 + nt * 8 + 2 * tig;
            float v00 = (acc[mt][nt][0] + bv0) * scale;
            float v01 = (acc[mt][nt][1] + bv0) * scale;
            float v10 = (acc[mt][nt][2] + bv1) * scale;
            float v11 = (acc[mt][nt][3] + bv1) * scale;
            uint32_t t00 = f2tf(v00), t01 = f2tf(v01);
            uint32_t t10 = f2tf(v10), t11 = f2tf(v11);
            if (which != 2) {
                uint32_t u00 = __shfl_xor_sync(0xffffffffu, t00, 16);
                uint32_t u01 = __shfl_xor_sync(0xffffffffu, t01, 16);
                uint32_t u10 = __shfl_xor_sync(0xffffffffu, t10, 16);
                uint32_t u11 = __shfl_xor_sync(0xffffffffu, t11, 16);
                if (l < 16) {
                    float* y0 = Y + (((size_t)b * NH + head) * T_DIM + c) * HD;
                    float* y1 = y0 + HD;
                    int o0 = mt * 16 + 2 * grp;
                    int o1 = o0 + 8;
                    *(float2*)&y0[o0] = make_float2(u2f(t00), u2f(u00));
                    *(float2*)&y1[o0] = make_float2(u2f(t01), u2f(u01));
                    *(float2*)&y0[o1] = make_float2(u2f(t10), u2f(u10));
                    *(float2*)&y1[o1] = make_float2(u2f(t11), u2f(u11));
                }
            } else {
                uint32_t u00 = __shfl_xor_sync(0xffffffffu, t00, 2);
                uint32_t u01 = __shfl_xor_sync(0xffffffffu, t01, 2);
                uint32_t u10 = __shfl_xor_sync(0xffffffffu, t10, 2);
                uint32_t u11 = __shfl_xor_sync(0xffffffffu, t11, 2);
                if (tig < 2) {
                    int d0 = mt * 16 + grp, d1 = d0 + 8;
                    int cb = n0 + wn * 64 + nt * 8 + 4 * tig;
                    float* z0 = Y + (((size_t)b * NH + head) * HD + d0) * T_DIM + cb;
                    float* z1 = Y + (((size_t)b * NH + head) * HD + d1) * T_DIM + cb;
                    *(float4*)z0 = make_float4(u2f(t00), u2f(u00), u2f(t01), u2f(u01));
                    *(float4*)z1 = make_float4(u2f(t10), u2f(u10), u2f(t11), u2f(u11));
                }
            }
        }
    }
}

// ---------------------------------------------------------------------------
// Output projection: Y[B,E,T] = Wo @ ao + bo.  N-tile 128 -> 256 blocks.
// W staged (pure copy from paired g_wp), ao B-frags direct LDG.64.
// ---------------------------------------------------------------------------
__global__ __launch_bounds__(256) void proj_out_kernel(
    const float* __restrict__ X, const float* __restrict__ Wo_p,
    const float* __restrict__ bias, float* __restrict__ Y)
{
    __shared__ __align__(16) float Ws[64][40];
    const int b  = blockIdx.z;
    const int m0 = blockIdx.y * 64;
    const int n0 = blockIdx.x * 128;
    const int tid = threadIdx.x;
    const int w = tid >> 5, l = tid & 31;
    const int wm = w >> 2, wn = w & 3;
    const int grp = l >> 2, tig = l & 3;

    float acc[2][4][4];
    #pragma unroll
    for (int mt = 0; mt < 2; mt++)
        #pragma unroll
        for (int nt = 0; nt < 4; nt++)
            #pragma unroll
            for (int j = 0; j < 4; j++) acc[mt][nt][j] = 0.f;

    for (int k0 = 0; k0 < E_DIM; k0 += 32) {
        __syncthreads();
        #pragma unroll
        for (int j = 0; j < 2; j++) {
            int idx = tid + j * 256;
            int r = idx >> 3, c4 = (idx & 7) * 4;
            *(float4*)&Ws[r][c4] = *(const float4*)&Wo_p[(size_t)(m0 + r) * E_DIM + k0 + c4];
        }
        __syncthreads();

        const int head = k0 >> 5;
        const float* xb1 = X + (((size_t)b * NH + head) * T_DIM + n0 + wn * 32 + grp) * HD;

        #pragma unroll
        for (int ks = 0; ks < 4; ks++) {
            const float* wrow = &Ws[wm * 32 + grp][ks * 8 + tig * 2];
            uint2 aL0 = *(const uint2*)(wrow);
            uint2 aL1 = *(const uint2*)(wrow + 8 * 40);
            uint2 aH0 = *(const uint2*)(wrow + 16 * 40);
            uint2 aH1 = *(const uint2*)(wrow + 24 * 40);
            uint32_t a0[4] = {aL0.x, aL1.x, aL0.y, aL1.y};
            uint32_t a1[4] = {aH0.x, aH1.x, aH0.y, aH1.y};
            #pragma unroll
            for (int nt = 0; nt < 4; nt++) {
                uint2 bb = *(const uint2*)(xb1 + (size_t)nt * 8 * HD + ks * 8 + 2 * tig);
                mma16n8k8(acc[0][nt], a0, bb.x, bb.y);
                mma16n8k8(acc[1][nt], a1, bb.x, bb.y);
            }
        }
    }

    #pragma unroll
    for (int mt = 0; mt < 2; mt++) {
        int r0 = m0 + wm * 32 + mt * 16 + grp;
        int r1 = r0 + 8;
        float bv0 = bias[r0], bv1 = bias[r1];
        #pragma unroll
        for (int nt = 0; nt < 4; nt++) {
            int c = n0 + wn * 32 + nt * 8 + 2 * tig;
            *(float2*)&Y[((size_t)b * E_DIM + r0) * T_DIM + c] =
                make_float2(acc[mt][nt][0] + bv0, acc[mt][nt][1] + bv0);
            *(float2*)&Y[((size_t)b * E_DIM + r1) * T_DIM + c] =
                make_float2(acc[mt][nt][2] + bv1, acc[mt][nt][3] + bv1);
        }
    }
}

// ---------------------------------------------------------------------------
// Warp-MMA (tf32) flash attention. cp.async K/V staging; mask as MMA1
// C-initializer (no adds, latency hidden behind staging wait).
// Block 128 thr (4 warps), q-tile 128 (warp: 32 q), key tiles of 64.
// ---------------------------------------------------------------------------
__global__ __launch_bounds__(128) void attn_mma_kernel(
    const float* __restrict__ Q, const float* __restrict__ K,
    const float* __restrict__ V, const float* __restrict__ mask,
    float* __restrict__ O)
{
    __shared__ __align__(16) float Ks[64][40];     // [s][k paired]
    __shared__ __align__(16) float Vt[32][72];     // [d][s paired]
    __shared__ __align__(16) float Pp[4][32][72];  // per-warp P [q][s paired]

    const int bh  = blockIdx.y;
    const int q0  = blockIdx.x * 128;
    const int tid = threadIdx.x;
    const int w   = tid >> 5;
    const int l   = tid & 31;
    const int grp = l >> 2;
    const int tig = l & 3;

    const uint32_t ks_a = smem_u32(&Ks[0][0]);
    const uint32_t vt_a = smem_u32(&Vt[0][0]);

    // ---- Q fragments: direct paired loads ----
    uint32_t qa[2][4][4];
    {
        const float* Qb = Q + ((size_t)bh * T_DIM + q0 + w * 32) * HD;
        #pragma unroll
        for (int mt = 0; mt < 2; mt++)
            #pragma unroll
            for (int ks = 0; ks < 4; ks++) {
                uint2 p0 = *(const uint2*)(Qb + (size_t)(mt * 16 + grp    ) * HD + ks * 8 + 2 * tig);
                uint2 p1 = *(const uint2*)(Qb + (size_t)(mt * 16 + grp + 8) * HD + ks * 8 + 2 * tig);
                qa[mt][ks][0] = p0.x; qa[mt][ks][1] = p1.x;
                qa[mt][ks][2] = p0.y; qa[mt][ks][3] = p1.y;
            }
    }

    float o_[2][4][4];
    #pragma unroll
    for (int mt = 0; mt < 2; mt++)
        #pragma unroll
        for (int nt = 0; nt < 4; nt++)
            #pragma unroll
            for (int j = 0; j < 4; j++) o_[mt][nt][j] = 0.f;

    float m_[4], l_[4];
    #pragma unroll
    for (int r = 0; r < 4; r++) { m_[r] = -CUDART_INF_F; l_[r] = 0.f; }

    const float* mr[4];
    #pragma unroll
    for (int r = 0; r < 4; r++)
        mr[r] = mask + (size_t)(q0 + w * 32 + (r >> 1) * 16 + (r & 1) * 8 + grp) * T_DIM;

    const int p0pos = pairpos(2 * tig) & 7;
    const int p1pos = pairpos(2 * tig + 1) & 7;

    for (int s0 = 0; s0 < T_DIM; s0 += 64) {
        __syncthreads();   // prior tile's smem reads complete
        // ---- cp.async stage K (64x32 paired) ----
        #pragma unroll
        for (int j = 0; j < 4; j++) {
            int idx = tid + j * 128;
            int r = idx >> 3, seg = idx & 7;
            cp_async16(ks_a + (r * 40 + seg * 4) * 4,
                       K + ((size_t)bh * T_DIM + s0 + r) * HD + seg * 4);
        }
        // ---- cp.async stage V (32d x 64s paired) ----
        #pragma unroll
        for (int j = 0; j < 4; j++) {
            int idx = tid + j * 128;
            int d = idx >> 4, seg = idx & 15;
            cp_async16(vt_a + (d * 72 + seg * 4) * 4,
                       V + ((size_t)bh * HD + d) * T_DIM + s0 + seg * 4);
        }
        CP_COMMIT();

        // ---- mask preload straight into MMA1 accumulators ----
        float sc[2][8][4];
        #pragma unroll
        for (int mt = 0; mt < 2; mt++)
            #pragma unroll
            for (int nt = 0; nt < 8; nt++) {
                float2 mk0 = __ldg((const float2*)&mr[mt * 2    ][s0 + nt * 8 + 2 * tig]);
                float2 mk1 = __ldg((const float2*)&mr[mt * 2 + 1][s0 + nt * 8 + 2 * tig]);
                sc[mt][nt][0] = mk0.x; sc[mt][nt][1] = mk0.y;
                sc[mt][nt][2] = mk1.x; sc[mt][nt][3] = mk1.y;
            }

        CP_WAIT0();
        __syncthreads();

        // ---- MMA1: sc += Q K^T ----
        #pragma unroll
        for (int nt = 0; nt < 8; nt++)
            #pragma unroll
            for (int ks = 0; ks < 4; ks++) {
                uint2 bb = *(const uint2*)&Ks[nt * 8 + grp][ks * 8 + tig * 2];
                mma16n8k8(sc[0][nt], qa[0][ks], bb.x, bb.y);
                mma16n8k8(sc[1][nt], qa[1][ks], bb.x, bb.y);
            }

        // ---- row max ----
        float mx[4] = {-CUDART_INF_F, -CUDART_INF_F, -CUDART_INF_F, -CUDART_INF_F};
        #pragma unroll
        for (int mt = 0; mt < 2; mt++)
            #pragma unroll
            for (int nt = 0; nt < 8; nt++) {
                mx[mt * 2]     = fmaxf(mx[mt * 2],     fmaxf(sc[mt][nt][0], sc[mt][nt][1]));
                mx[mt * 2 + 1] = fmaxf(mx[mt * 2 + 1], fmaxf(sc[mt][nt][2], sc[mt][nt][3]));
            }
        #pragma unroll
        for (int r = 0; r < 4; r++) {
            mx[r] = fmaxf(mx[r], __shfl_xor_sync(0xffffffffu, mx[r], 1));
            mx[r] = fmaxf(mx[r], __shfl_xor_sync(0xffffffffu, mx[r], 2));
        }
        float corr[4], sum[4];
        #pragma unroll
        for (int r = 0; r < 4; r++) {
            float mn = fmaxf(m_[r], mx[r]);
            corr[r] = __expf(m_[r] - mn);
            m_[r] = mn;
            sum[r] = 0.f;
        }

        // ---- exp + P store (tf32, paired layout) ----
        #pragma unroll
        for (int mt = 0; mt < 2; mt++)
            #pragma unroll
            for (int nt = 0; nt < 8; nt++) {
                float p0 = __expf(sc[mt][nt][0] - m_[mt * 2]);
                float p1 = __expf(sc[mt][nt][1] - m_[mt * 2]);
                float p2 = __expf(sc[mt][nt][2] - m_[mt * 2 + 1]);
                float p3 = __expf(sc[mt][nt][3] - m_[mt * 2 + 1]);
                sum[mt * 2]     += p0 + p1;
                sum[mt * 2 + 1] += p2 + p3;
                Pp[w][mt * 16 + grp    ][nt * 8 + p0pos] = u2f(f2tf(p0));
                Pp[w][mt * 16 + grp    ][nt * 8 + p1pos] = u2f(f2tf(p1));
                Pp[w][mt * 16 + grp + 8][nt * 8 + p0pos] = u2f(f2tf(p2));
                Pp[w][mt * 16 + grp + 8][nt * 8 + p1pos] = u2f(f2tf(p3));
            }
        #pragma unroll
        for (int r = 0; r < 4; r++) {
            sum[r] += __shfl_xor_sync(0xffffffffu, sum[r], 1);
            sum[r] += __shfl_xor_sync(0xffffffffu, sum[r], 2);
            l_[r] = l_[r] * corr[r] + sum[r];
        }
        #pragma unroll
        for (int mt = 0; mt < 2; mt++)
            #pragma unroll
            for (int nt = 0; nt < 4; nt++) {
                o_[mt][nt][0] *= corr[mt * 2];     o_[mt][nt][1] *= corr[mt * 2];
                o_[mt][nt][2] *= corr[mt * 2 + 1]; o_[mt][nt][3] *= corr[mt * 2 + 1];
            }
        __syncwarp();

        // ---- MMA2: O(32x32) += P(32x64) V(64x32) ----
        #pragma unroll
        for (int ks = 0; ks < 8; ks++) {
            uint2 aL0 = *(const uint2*)&Pp[w][grp     ][ks * 8 + tig * 2];
            uint2 aL1 = *(const uint2*)&Pp[w][grp + 8 ][ks * 8 + tig * 2];
            uint2 aH0 = *(const uint2*)&Pp[w][grp + 16][ks * 8 + tig * 2];
            uint2 aH1 = *(const uint2*)&Pp[w][grp + 24][ks * 8 + tig * 2];
            uint32_t a0[4] = {aL0.x, aL1.x, aL0.y, aL1.y};
            uint32_t a1[4] = {aH0.x, aH1.x, aH0.y, aH1.y};
            #pragma unroll
            for (int nt = 0; nt < 4; nt++) {
                uint2 bb = *(const uint2*)&Vt[nt * 8 + grp][ks * 8 + tig * 2];
                mma16n8k8(o_[0][nt], a0, bb.x, bb.y);
                mma16n8k8(o_[1][nt], a1, bb.x, bb.y);
            }
        }
        __syncwarp();
    }

    // ---- epilogue: ao tf32-paired [bh][t][pp(d)] ----
    #pragma unroll
    for (int mt = 0; mt < 2; mt++) {
        float i0 = 1.f / l_[mt * 2], i1 = 1.f / l_[mt * 2 + 1];
        #pragma unroll
        for (int nt = 0; nt < 4; nt++) {
            uint32_t t0 = f2tf(o_[mt][nt][0] * i0), t1 = f2tf(o_[mt][nt][1] * i0);
            uint32_t t2 = f2tf(o_[mt][nt][2] * i1), t3 = f2tf(o_[mt][nt][3] * i1);
            uint32_t u0 = __shfl_xor_sync(0xffffffffu, t0, 2);
            uint32_t u1 = __shfl_xor_sync(0xffffffffu, t1, 2);
            uint32_t u2 = __shfl_xor_sync(0xffffffffu, t2, 2);
            uint32_t u3 = __shfl_xor_sync(0xffffffffu, t3, 2);
            if (tig < 2) {
                size_t r0 = (size_t)bh * T_DIM + q0 + w * 32 + mt * 16 + grp;
                float* z0 = O + r0 * HD + nt * 8 + 4 * tig;
                float* z1 = z0 + 8 * HD;
                *(float4*)z0 = make_float4(u2f(t0), u2f(u0), u2f(t1), u2f(u1));
                *(float4*)z1 = make_float4(u2f(t2), u2f(u2), u2f(t3), u2f(u3));
            }
        }
    }
}

// ---------------------------------------------------------------------------
extern "C" void kernel_launch(void* const* d_in, const int* in_sizes, int n_in,
                              void* d_out, int out_size)
{
    // metadata order: 0:query 1:key 2:value 3:attn_mask
    //                 4:Wq 5:Wk 6:Wv 7:Wo  8:bq 9:bk 10:bv 11:bo
    const float* query = (const float*)d_in[0];
    const float* key   = (const float*)d_in[1];
    const float* value = (const float*)d_in[2];
    const float* mask  = (const float*)d_in[3];
    const float* Wq    = (const float*)d_in[4];
    const float* Wk    = (const float*)d_in[5];
    const float* Wv    = (const float*)d_in[6];
    const float* Wo    = (const float*)d_in[7];
    const float* bq    = (const float*)d_in[8];
    const float* bk    = (const float*)d_in[9];
    const float* bv    = (const float*)d_in[10];
    const float* bo    = (const float*)d_in[11];
    float* out = (float*)d_out;

    static float *q_buf = nullptr, *k_buf, *v_buf, *ao_buf, *xt, *wp;
    if (!q_buf) {
        void* p;
        cudaGetSymbolAddress(&p, g_q);  q_buf  = (float*)p;
        cudaGetSymbolAddress(&p, g_k);  k_buf  = (float*)p;
        cudaGetSymbolAddress(&p, g_v);  v_buf  = (float*)p;
        cudaGetSymbolAddress(&p, g_ao); ao_buf = (float*)p;
        cudaGetSymbolAddress(&p, g_xt); xt = (float*)p;
        cudaGetSymbolAddress(&p, g_wp); wp = (float*)p;
        cudaFuncSetAttribute(proj_qkv_kernel,
                             cudaFuncAttributeMaxDynamicSharedMemorySize, 102400);
    }

    const float scale = 0.17677669529663687f;  // 32^-0.5, folded into Q proj

    // 1) weight pre-convert (paired tf32)
    wcvt_kernel<<<dim3(E_DIM, 4), E_DIM / 4>>>(Wq, Wk, Wv, Wo, wp);

    // 2) input transpose+convert -> [tensor][b][t][pp(e)]
    xt_kernel<<<dim3(T_DIM / 64, E_DIM / 64, 24), 256>>>(query, key, value, xt);

    // 3) QKV projections (cp.async double-buffered)
    proj_qkv_kernel<<<dim3(T_DIM / 256, E_DIM / 64, 24), 256, 102400>>>(
        xt, wp, bq, bk, bv, q_buf, k_buf, v_buf, scale);

    // 4) attention
    attn_mma_kernel<<<dim3(T_DIM / 128, BHTOT), 128>>>(q_buf, k_buf, v_buf, mask, ao_buf);

    // 5) output projection
    proj_out_kernel<<<dim3(T_DIM / 128, E_DIM / 64, B_DIM), 256>>>(
        ao_buf, wp + 3 * E_DIM * E_DIM, bo, out);
}

// round 15
// speedup vs baseline: 5.1260x; 1.1251x over previous
#include <cuda_runtime.h>
#include <math_constants.h>
#include <cstdint>

#define E_DIM 256
#define T_DIM 1024
#define NH 8
#define HD 32
#define B_DIM 8
#define BHTOT 64   // B*NH

// Scratch (no allocations allowed). tf32-bit floats:
//  g_q, g_k : [bh][t][pp(d)]   g_v : [bh][d][t] (natural)   g_ao : [bh][t][pp(d)]
//  g_xt     : [tensor][b][t][pp(e)]  (transposed, paired, tf32)
//  g_wp     : [4][m][pp(k)]          (paired tf32 weights q,k,v,o)
__device__ float g_q [BHTOT * T_DIM * HD];
__device__ float g_k [BHTOT * T_DIM * HD];
__device__ float g_v [BHTOT * T_DIM * HD];
__device__ float g_ao[BHTOT * T_DIM * HD];
__device__ float g_xt[3u * B_DIM * T_DIM * E_DIM];
__device__ float g_wp[4 * E_DIM * E_DIM];

// ===========================================================================
__device__ __forceinline__ uint32_t f2tf(float x) {
    uint32_t r;
    asm("cvt.rna.tf32.f32 %0, %1;" : "=r"(r) : "f"(x));
    return r;
}
__device__ __forceinline__ float u2f(uint32_t x) { return __uint_as_float(x); }

__device__ __forceinline__ void mma16n8k8(float c[4], const uint32_t a[4],
                                          uint32_t b0, uint32_t b1) {
    asm volatile(
        "mma.sync.aligned.m16n8k8.row.col.f32.tf32.tf32.f32 "
        "{%0,%1,%2,%3}, {%4,%5,%6,%7}, {%8,%9}, {%0,%1,%2,%3};"
        : "+f"(c[0]), "+f"(c[1]), "+f"(c[2]), "+f"(c[3])
        : "r"(a[0]), "r"(a[1]), "r"(a[2]), "r"(a[3]), "r"(b0), "r"(b1));
}

// paired position: within aligned 8-blocks, order (0,4),(1,5),(2,6),(3,7)
__device__ __forceinline__ int pairpos(int k) {
    return (k & ~7) | ((k & 3) << 1) | ((k >> 2) & 1);
}
// inverse: source k for paired position p
__device__ __forceinline__ int srck(int p) {
    return (p & ~7) | ((p & 7) >> 1) | ((p & 1) << 2);
}

__device__ __forceinline__ uint32_t smem_u32(const void* p) {
    uint32_t a;
    asm("{ .reg .u64 t; cvta.to.shared.u64 t, %1; cvt.u32.u64 %0, t; }" : "=r"(a) : "l"(p));
    return a;
}
__device__ __forceinline__ void cp_async16(uint32_t dst, const void* src) {
    asm volatile("cp.async.ca.shared.global [%0], [%1], 16;" :: "r"(dst), "l"(src));
}
#define CP_COMMIT() asm volatile("cp.async.commit_group;" ::: "memory")
#define CP_WAIT0()  asm volatile("cp.async.wait_group 0;" ::: "memory")
#define CP_WAIT1()  asm volatile("cp.async.wait_group 1;" ::: "memory")

// ---------------------------------------------------------------------------
// Weight pre-convert: W[m][k] fp32 -> g_wp[wi][m][pp(k)] tf32 bits.
// ---------------------------------------------------------------------------
__global__ void wcvt_kernel(const float* __restrict__ Wq, const float* __restrict__ Wk,
                            const float* __restrict__ Wv, const float* __restrict__ Wo,
                            float* __restrict__ out)
{
    const float* W = (blockIdx.y == 0) ? Wq : (blockIdx.y == 1) ? Wk
                   : (blockIdx.y == 2) ? Wv : Wo;
    int m = blockIdx.x;
    int p = threadIdx.x * 4;
    const float* row = W + (size_t)m * E_DIM;
    float4 v;
    v.x = u2f(f2tf(row[srck(p + 0)]));
    v.y = u2f(f2tf(row[srck(p + 1)]));
    v.z = u2f(f2tf(row[srck(p + 2)]));
    v.w = u2f(f2tf(row[srck(p + 3)]));
    *(float4*)(out + ((size_t)blockIdx.y * E_DIM + m) * E_DIM + p) = v;
}

// ---------------------------------------------------------------------------
// Input transpose+convert: X[b][e][t] fp32 -> g_xt[tensor][b][t][pp(e)] tf32.
// ---------------------------------------------------------------------------
__global__ __launch_bounds__(256) void xt_kernel(
    const float* __restrict__ q, const float* __restrict__ k,
    const float* __restrict__ v, float* __restrict__ out)
{
    __shared__ float Ts[64][65];
    const int tz = blockIdx.z;
    const int tensor = tz >> 3, b = tz & 7;
    const float* X = (tensor == 0) ? q : (tensor == 1) ? k : v;
    const int e0 = blockIdx.y * 64, t0 = blockIdx.x * 64;
    const int tid = threadIdx.x;

    #pragma unroll
    for (int j = 0; j < 4; j++) {
        int e  = (tid >> 4) + j * 16;
        int t4 = (tid & 15) * 4;
        float4 val = *(const float4*)&X[((size_t)b * E_DIM + e0 + e) * T_DIM + t0 + t4];
        Ts[e][t4 + 0] = val.x; Ts[e][t4 + 1] = val.y;
        Ts[e][t4 + 2] = val.z; Ts[e][t4 + 3] = val.w;
    }
    __syncthreads();
    float* ob = out + (size_t)tensor * (B_DIM * T_DIM * E_DIM)
              + ((size_t)b * T_DIM + t0) * E_DIM + e0;
    #pragma unroll
    for (int j = 0; j < 8; j++) {
        int t = (tid >> 5) + j * 8;
        int e = tid & 31;
        ob[(size_t)t * E_DIM + pairpos(e)]      = u2f(f2tf(Ts[e][t]));
        ob[(size_t)t * E_DIM + pairpos(e + 32)] = u2f(f2tf(Ts[e + 32][t]));
    }
}

// ---------------------------------------------------------------------------
// QKV projection, cp.async double-buffered, all-tf32-paired operands.
// Block 256 (8 warps: 2m x 4n), tile M=64 x N=256, K-chunk 32, 8 chunks.
// Outputs: q/k paired [bh][t][pp(d)]; v natural [bh][d][t].
// ---------------------------------------------------------------------------
#define QKV_STAGE(KK0, BUF) do {                                               \
    _Pragma("unroll")                                                          \
    for (int j = 0; j < 8; j++) {                                              \
        int r = (tid >> 3) + j * 32;                                           \
        int seg = tid & 7;                                                     \
        cp_async16(xs_a + (((BUF) * 256 + r) * 40 + seg * 4) * 4,              \
                   Xb + (size_t)(n0 + r) * E_DIM + (KK0) + seg * 4);           \
    }                                                                          \
    _Pragma("unroll")                                                          \
    for (int j = 0; j < 2; j++) {                                              \
        int r = (tid >> 3) + j * 32;                                           \
        int seg = tid & 7;                                                     \
        cp_async16(ws_a + (((BUF) * 64 + r) * 40 + seg * 4) * 4,               \
                   Wm + (size_t)(m0 + r) * E_DIM + (KK0) + seg * 4);           \
    }                                                                          \
    CP_COMMIT();                                                               \
} while (0)

__global__ __launch_bounds__(256) void proj_qkv_kernel(
    const float* __restrict__ Xt, const float* __restrict__ Wp,
    const float* __restrict__ bq, const float* __restrict__ bk,
    const float* __restrict__ bv,
    float* __restrict__ Yq, float* __restrict__ Yk, float* __restrict__ Yv,
    float scale0)
{
    extern __shared__ float sm[];
    float* Xs  = sm;                 // [2][256][40]
    float* Wsm = sm + 2 * 256 * 40;  // [2][64][40]

    const int zz = blockIdx.z;
    const int b = zz & 7, which = zz >> 3;
    const float* Xb = Xt + (((size_t)which * B_DIM + b) * T_DIM) * E_DIM;
    const float* Wm = Wp + (size_t)which * E_DIM * E_DIM;
    const float* bias = (which == 0) ? bq : (which == 1) ? bk : bv;
    float* Y = (which == 0) ? Yq : (which == 1) ? Yk : Yv;
    const float scale = (which == 0) ? scale0 : 1.0f;

    const int m0 = blockIdx.y * 64;
    const int n0 = blockIdx.x * 256;
    const int tid = threadIdx.x;
    const int w = tid >> 5, l = tid & 31;
    const int wm = w >> 2, wn = w & 3;
    const int grp = l >> 2, tig = l & 3;

    const uint32_t xs_a = smem_u32(Xs);
    const uint32_t ws_a = smem_u32(Wsm);

    float acc[2][8][4];
    #pragma unroll
    for (int mt = 0; mt < 2; mt++)
        #pragma unroll
        for (int nt = 0; nt < 8; nt++)
            #pragma unroll
            for (int j = 0; j < 4; j++) acc[mt][nt][j] = 0.f;

    QKV_STAGE(0, 0);

    for (int c = 0; c < 8; c++) {
        const int buf = c & 1;
        if (c < 7) { QKV_STAGE((c + 1) * 32, buf ^ 1); CP_WAIT1(); }
        else       { CP_WAIT0(); }
        __syncthreads();

        #pragma unroll
        for (int ks = 0; ks < 4; ks++) {
            const float* wrow = &Wsm[(buf * 64 + wm * 32 + grp) * 40 + ks * 8 + tig * 2];
            uint2 aL0 = *(const uint2*)(wrow);
            uint2 aL1 = *(const uint2*)(wrow + 8 * 40);
            uint2 aH0 = *(const uint2*)(wrow + 16 * 40);
            uint2 aH1 = *(const uint2*)(wrow + 24 * 40);
            uint32_t a0[4] = {aL0.x, aL1.x, aL0.y, aL1.y};
            uint32_t a1[4] = {aH0.x, aH1.x, aH0.y, aH1.y};
            #pragma unroll
            for (int nt = 0; nt < 8; nt++) {
                uint2 bb = *(const uint2*)&Xs[(buf * 256 + wn * 64 + nt * 8 + grp) * 40
                                              + ks * 8 + tig * 2];
                mma16n8k8(acc[0][nt], a0, bb.x, bb.y);
                mma16n8k8(acc[1][nt], a1, bb.x, bb.y);
            }
        }
        __syncthreads();
    }

    // ---- epilogue (tf32 outputs) ----
    const int head = (m0 + wm * 32) >> 5;
    #pragma unroll
    for (int mt = 0; mt < 2; mt++) {
        int r0 = m0 + wm * 32 + mt * 16 + grp;
        int r1 = r0 + 8;
        float bv0 = bias[r0], bv1 = bias[r1];
        #pragma unroll
        for (int nt = 0; nt < 8; nt++) {
            int c = n0 + wn * 64 + nt * 8 + 2 * tig;
            float v00 = (acc[mt][nt][0] + bv0) * scale;
            float v01 = (acc[mt][nt][1] + bv0) * scale;
            float v10 = (acc[mt][nt][2] + bv1) * scale;
            float v11 = (acc[mt][nt][3] + bv1) * scale;
            uint32_t t00 = f2tf(v00), t01 = f2tf(v01);
            uint32_t t10 = f2tf(v10), t11 = f2tf(v11);
            if (which != 2) {
                // q/k: pair channels (d, d+4): partner lane = l ^ 16
                uint32_t u00 = __shfl_xor_sync(0xffffffffu, t00, 16);
                uint32_t u01 = __shfl_xor_sync(0xffffffffu, t01, 16);
                uint32_t u10 = __shfl_xor_sync(0xffffffffu, t10, 16);
                uint32_t u11 = __shfl_xor_sync(0xffffffffu, t11, 16);
                if (l < 16) {
                    float* y0 = Y + (((size_t)b * NH + head) * T_DIM + c) * HD;
                    float* y1 = y0 + HD;
                    int o0 = mt * 16 + 2 * grp;
                    int o1 = o0 + 8;
                    *(float2*)&y0[o0] = make_float2(u2f(t00), u2f(u00));
                    *(float2*)&y1[o0] = make_float2(u2f(t01), u2f(u01));
                    *(float2*)&y0[o1] = make_float2(u2f(t10), u2f(u10));
                    *(float2*)&y1[o1] = make_float2(u2f(t11), u2f(u11));
                }
            } else {
                // V: natural [bh][d][t], adjacent tokens -> direct float2
                int d0 = mt * 16 + grp, d1 = d0 + 8;
                float* z0 = Y + (((size_t)b * NH + head) * HD + d0) * T_DIM + c;
                float* z1 = Y + (((size_t)b * NH + head) * HD + d1) * T_DIM + c;
                *(float2*)z0 = make_float2(u2f(t00), u2f(t01));
                *(float2*)z1 = make_float2(u2f(t10), u2f(t11));
            }
        }
    }
}

// ---------------------------------------------------------------------------
// Output projection: Y[B,E,T] = Wo @ ao + bo.
// ---------------------------------------------------------------------------
__global__ __launch_bounds__(256) void proj_out_kernel(
    const float* __restrict__ X, const float* __restrict__ Wo_p,
    const float* __restrict__ bias, float* __restrict__ Y)
{
    __shared__ __align__(16) float Ws[64][40];
    const int b  = blockIdx.z;
    const int m0 = blockIdx.y * 64;
    const int n0 = blockIdx.x * 128;
    const int tid = threadIdx.x;
    const int w = tid >> 5, l = tid & 31;
    const int wm = w >> 2, wn = w & 3;
    const int grp = l >> 2, tig = l & 3;

    float acc[2][4][4];
    #pragma unroll
    for (int mt = 0; mt < 2; mt++)
        #pragma unroll
        for (int nt = 0; nt < 4; nt++)
            #pragma unroll
            for (int j = 0; j < 4; j++) acc[mt][nt][j] = 0.f;

    for (int k0 = 0; k0 < E_DIM; k0 += 32) {
        __syncthreads();
        #pragma unroll
        for (int j = 0; j < 2; j++) {
            int idx = tid + j * 256;
            int r = idx >> 3, c4 = (idx & 7) * 4;
            *(float4*)&Ws[r][c4] = *(const float4*)&Wo_p[(size_t)(m0 + r) * E_DIM + k0 + c4];
        }
        __syncthreads();

        const int head = k0 >> 5;
        const float* xb1 = X + (((size_t)b * NH + head) * T_DIM + n0 + wn * 32 + grp) * HD;

        #pragma unroll
        for (int ks = 0; ks < 4; ks++) {
            const float* wrow = &Ws[wm * 32 + grp][ks * 8 + tig * 2];
            uint2 aL0 = *(const uint2*)(wrow);
            uint2 aL1 = *(const uint2*)(wrow + 8 * 40);
            uint2 aH0 = *(const uint2*)(wrow + 16 * 40);
            uint2 aH1 = *(const uint2*)(wrow + 24 * 40);
            uint32_t a0[4] = {aL0.x, aL1.x, aL0.y, aL1.y};
            uint32_t a1[4] = {aH0.x, aH1.x, aH0.y, aH1.y};
            #pragma unroll
            for (int nt = 0; nt < 4; nt++) {
                uint2 bb = *(const uint2*)(xb1 + (size_t)nt * 8 * HD + ks * 8 + 2 * tig);
                mma16n8k8(acc[0][nt], a0, bb.x, bb.y);
                mma16n8k8(acc[1][nt], a1, bb.x, bb.y);
            }
        }
    }

    #pragma unroll
    for (int mt = 0; mt < 2; mt++) {
        int r0 = m0 + wm * 32 + mt * 16 + grp;
        int r1 = r0 + 8;
        float bv0 = bias[r0], bv1 = bias[r1];
        #pragma unroll
        for (int nt = 0; nt < 4; nt++) {
            int c = n0 + wn * 32 + nt * 8 + 2 * tig;
            *(float2*)&Y[((size_t)b * E_DIM + r0) * T_DIM + c] =
                make_float2(acc[mt][nt][0] + bv0, acc[mt][nt][1] + bv0);
            *(float2*)&Y[((size_t)b * E_DIM + r1) * T_DIM + c] =
                make_float2(acc[mt][nt][2] + bv1, acc[mt][nt][3] + bv1);
        }
    }
}

// ---------------------------------------------------------------------------
// Warp-MMA (tf32) flash attention — P stays in registers.
// MMA1 C-frag {c0,c1;c2,c3} = rows(grp,grp+8) x cols(2tig,2tig+1).
// Relabel as MMA2 A-frag a={c0,c2,c1,c3} (k-slots tig,tig+4 hold keys
// 2tig,2tig+1); V stored in natural token order supplies exactly those keys
// at those slots via the uint2 B-frag read. No P smem, no syncwarp.
// ---------------------------------------------------------------------------
__global__ __launch_bounds__(128) void attn_mma_kernel(
    const float* __restrict__ Q, const float* __restrict__ K,
    const float* __restrict__ V, const float* __restrict__ mask,
    float* __restrict__ O)
{
    __shared__ __align__(16) float Ks[64][40];     // [s][k paired]
    __shared__ __align__(16) float Vt[32][72];     // [d][s natural]

    const int bh  = blockIdx.y;
    const int q0  = blockIdx.x * 128;
    const int tid = threadIdx.x;
    const int w   = tid >> 5;
    const int l   = tid & 31;
    const int grp = l >> 2;
    const int tig = l & 3;

    const uint32_t ks_a = smem_u32(&Ks[0][0]);
    const uint32_t vt_a = smem_u32(&Vt[0][0]);

    // ---- Q fragments: direct paired loads ----
    uint32_t qa[2][4][4];
    {
        const float* Qb = Q + ((size_t)bh * T_DIM + q0 + w * 32) * HD;
        #pragma unroll
        for (int mt = 0; mt < 2; mt++)
            #pragma unroll
            for (int ks = 0; ks < 4; ks++) {
                uint2 p0 = *(const uint2*)(Qb + (size_t)(mt * 16 + grp    ) * HD + ks * 8 + 2 * tig);
                uint2 p1 = *(const uint2*)(Qb + (size_t)(mt * 16 + grp + 8) * HD + ks * 8 + 2 * tig);
                qa[mt][ks][0] = p0.x; qa[mt][ks][1] = p1.x;
                qa[mt][ks][2] = p0.y; qa[mt][ks][3] = p1.y;
            }
    }

    float o_[2][4][4];
    #pragma unroll
    for (int mt = 0; mt < 2; mt++)
        #pragma unroll
        for (int nt = 0; nt < 4; nt++)
            #pragma unroll
            for (int j = 0; j < 4; j++) o_[mt][nt][j] = 0.f;

    float m_[4], l_[4];
    #pragma unroll
    for (int r = 0; r < 4; r++) { m_[r] = -CUDART_INF_F; l_[r] = 0.f; }

    const float* mr[4];
    #pragma unroll
    for (int r = 0; r < 4; r++)
        mr[r] = mask + (size_t)(q0 + w * 32 + (r >> 1) * 16 + (r & 1) * 8 + grp) * T_DIM;

    for (int s0 = 0; s0 < T_DIM; s0 += 64) {
        __syncthreads();   // prior tile's smem reads complete
        // ---- cp.async stage K (64x32 paired) ----
        #pragma unroll
        for (int j = 0; j < 4; j++) {
            int idx = tid + j * 128;
            int r = idx >> 3, seg = idx & 7;
            cp_async16(ks_a + (r * 40 + seg * 4) * 4,
                       K + ((size_t)bh * T_DIM + s0 + r) * HD + seg * 4);
        }
        // ---- cp.async stage V (32d x 64s natural) ----
        #pragma unroll
        for (int j = 0; j < 4; j++) {
            int idx = tid + j * 128;
            int d = idx >> 4, seg = idx & 15;
            cp_async16(vt_a + (d * 72 + seg * 4) * 4,
                       V + ((size_t)bh * HD + d) * T_DIM + s0 + seg * 4);
        }
        CP_COMMIT();

        // ---- mask preload straight into MMA1 accumulators ----
        float sc[2][8][4];
        #pragma unroll
        for (int mt = 0; mt < 2; mt++)
            #pragma unroll
            for (int nt = 0; nt < 8; nt++) {
                float2 mk0 = __ldg((const float2*)&mr[mt * 2    ][s0 + nt * 8 + 2 * tig]);
                float2 mk1 = __ldg((const float2*)&mr[mt * 2 + 1][s0 + nt * 8 + 2 * tig]);
                sc[mt][nt][0] = mk0.x; sc[mt][nt][1] = mk0.y;
                sc[mt][nt][2] = mk1.x; sc[mt][nt][3] = mk1.y;
            }

        CP_WAIT0();
        __syncthreads();

        // ---- MMA1: sc += Q K^T ----
        #pragma unroll
        for (int nt = 0; nt < 8; nt++)
            #pragma unroll
            for (int ks = 0; ks < 4; ks++) {
                uint2 bb = *(const uint2*)&Ks[nt * 8 + grp][ks * 8 + tig * 2];
                mma16n8k8(sc[0][nt], qa[0][ks], bb.x, bb.y);
                mma16n8k8(sc[1][nt], qa[1][ks], bb.x, bb.y);
            }

        // ---- row max ----
        float mx[4] = {-CUDART_INF_F, -CUDART_INF_F, -CUDART_INF_F, -CUDART_INF_F};
        #pragma unroll
        for (int mt = 0; mt < 2; mt++)
            #pragma unroll
            for (int nt = 0; nt < 8; nt++) {
                mx[mt * 2]     = fmaxf(mx[mt * 2],     fmaxf(sc[mt][nt][0], sc[mt][nt][1]));
                mx[mt * 2 + 1] = fmaxf(mx[mt * 2 + 1], fmaxf(sc[mt][nt][2], sc[mt][nt][3]));
            }
        #pragma unroll
        for (int r = 0; r < 4; r++) {
            mx[r] = fmaxf(mx[r], __shfl_xor_sync(0xffffffffu, mx[r], 1));
            mx[r] = fmaxf(mx[r], __shfl_xor_sync(0xffffffffu, mx[r], 2));
        }
        float corr[4], sum[4];
        #pragma unroll
        for (int r = 0; r < 4; r++) {
            float mn = fmaxf(m_[r], mx[r]);
            corr[r] = __expf(m_[r] - mn);
            m_[r] = mn;
            sum[r] = 0.f;
        }

        // ---- exp in place (P stays in sc registers) ----
        #pragma unroll
        for (int mt = 0; mt < 2; mt++)
            #pragma unroll
            for (int nt = 0; nt < 8; nt++) {
                float p0 = __expf(sc[mt][nt][0] - m_[mt * 2]);
                float p1 = __expf(sc[mt][nt][1] - m_[mt * 2]);
                float p2 = __expf(sc[mt][nt][2] - m_[mt * 2 + 1]);
                float p3 = __expf(sc[mt][nt][3] - m_[mt * 2 + 1]);
                sum[mt * 2]     += p0 + p1;
                sum[mt * 2 + 1] += p2 + p3;
                sc[mt][nt][0] = p0; sc[mt][nt][1] = p1;
                sc[mt][nt][2] = p2; sc[mt][nt][3] = p3;
            }
        #pragma unroll
        for (int r = 0; r < 4; r++) {
            sum[r] += __shfl_xor_sync(0xffffffffu, sum[r], 1);
            sum[r] += __shfl_xor_sync(0xffffffffu, sum[r], 2);
            l_[r] = l_[r] * corr[r] + sum[r];
        }
        #pragma unroll
        for (int mt = 0; mt < 2; mt++)
            #pragma unroll
            for (int nt = 0; nt < 4; nt++) {
                o_[mt][nt][0] *= corr[mt * 2];     o_[mt][nt][1] *= corr[mt * 2];
                o_[mt][nt][2] *= corr[mt * 2 + 1]; o_[mt][nt][3] *= corr[mt * 2 + 1];
            }

        // ---- MMA2: O(32x32) += P(32x64) V(64x32), A-frags from sc regs ----
        #pragma unroll
        for (int ks = 0; ks < 8; ks++) {
            uint32_t a0[4] = {f2tf(sc[0][ks][0]), f2tf(sc[0][ks][2]),
                              f2tf(sc[0][ks][1]), f2tf(sc[0][ks][3])};
            uint32_t a1[4] = {f2tf(sc[1][ks][0]), f2tf(sc[1][ks][2]),
                              f2tf(sc[1][ks][1]), f2tf(sc[1][ks][3])};
            #pragma unroll
            for (int nt = 0; nt < 4; nt++) {
                uint2 bb = *(const uint2*)&Vt[nt * 8 + grp][ks * 8 + tig * 2];
                mma16n8k8(o_[0][nt], a0, bb.x, bb.y);
                mma16n8k8(o_[1][nt], a1, bb.x, bb.y);
            }
        }
    }

    // ---- epilogue: ao tf32-paired [bh][t][pp(d)] ----
    #pragma unroll
    for (int mt = 0; mt < 2; mt++) {
        float i0 = 1.f / l_[mt * 2], i1 = 1.f / l_[mt * 2 + 1];
        #pragma unroll
        for (int nt = 0; nt < 4; nt++) {
            uint32_t t0 = f2tf(o_[mt][nt][0] * i0), t1 = f2tf(o_[mt][nt][1] * i0);
            uint32_t t2 = f2tf(o_[mt][nt][2] * i1), t3 = f2tf(o_[mt][nt][3] * i1);
            uint32_t u0 = __shfl_xor_sync(0xffffffffu, t0, 2);
            uint32_t u1 = __shfl_xor_sync(0xffffffffu, t1, 2);
            uint32_t u2 = __shfl_xor_sync(0xffffffffu, t2, 2);
            uint32_t u3 = __shfl_xor_sync(0xffffffffu, t3, 2);
            if (tig < 2) {
                size_t r0 = (size_t)bh * T_DIM + q0 + w * 32 + mt * 16 + grp;
                float* z0 = O + r0 * HD + nt * 8 + 4 * tig;
                float* z1 = z0 + 8 * HD;
                *(float4*)z0 = make_float4(u2f(t0), u2f(u0), u2f(t1), u2f(u1));
                *(float4*)z1 = make_float4(u2f(t2), u2f(u2), u2f(t3), u2f(u3));
            }
        }
    }
}

// ---------------------------------------------------------------------------
extern "C" void kernel_launch(void* const* d_in, const int* in_sizes, int n_in,
                              void* d_out, int out_size)
{
    // metadata order: 0:query 1:key 2:value 3:attn_mask
    //                 4:Wq 5:Wk 6:Wv 7:Wo  8:bq 9:bk 10:bv 11:bo
    const float* query = (const float*)d_in[0];
    const float* key   = (const float*)d_in[1];
    const float* value = (const float*)d_in[2];
    const float* mask  = (const float*)d_in[3];
    const float* Wq    = (const float*)d_in[4];
    const float* Wk    = (const float*)d_in[5];
    const float* Wv    = (const float*)d_in[6];
    const float* Wo    = (const float*)d_in[7];
    const float* bq    = (const float*)d_in[8];
    const float* bk    = (const float*)d_in[9];
    const float* bv    = (const float*)d_in[10];
    const float* bo    = (const float*)d_in[11];
    float* out = (float*)d_out;

    static float *q_buf = nullptr, *k_buf, *v_buf, *ao_buf, *xt, *wp;
    if (!q_buf) {
        void* p;
        cudaGetSymbolAddress(&p, g_q);  q_buf  = (float*)p;
        cudaGetSymbolAddress(&p, g_k);  k_buf  = (float*)p;
        cudaGetSymbolAddress(&p, g_v);  v_buf  = (float*)p;
        cudaGetSymbolAddress(&p, g_ao); ao_buf = (float*)p;
        cudaGetSymbolAddress(&p, g_xt); xt = (float*)p;
        cudaGetSymbolAddress(&p, g_wp); wp = (float*)p;
        cudaFuncSetAttribute(proj_qkv_kernel,
                             cudaFuncAttributeMaxDynamicSharedMemorySize, 102400);
    }

    const float scale = 0.17677669529663687f;  // 32^-0.5, folded into Q proj

    // 1) weight pre-convert (paired tf32)
    wcvt_kernel<<<dim3(E_DIM, 4), E_DIM / 4>>>(Wq, Wk, Wv, Wo, wp);

    // 2) input transpose+convert -> [tensor][b][t][pp(e)]
    xt_kernel<<<dim3(T_DIM / 64, E_DIM / 64, 24), 256>>>(query, key, value, xt);

    // 3) QKV projections (cp.async double-buffered)
    proj_qkv_kernel<<<dim3(T_DIM / 256, E_DIM / 64, 24), 256, 102400>>>(
        xt, wp, bq, bk, bv, q_buf, k_buf, v_buf, scale);

    // 4) attention
    attn_mma_kernel<<<dim3(T_DIM / 128, BHTOT), 128>>>(q_buf, k_buf, v_buf, mask, ao_buf);

    // 5) output projection
    proj_out_kernel<<<dim3(T_DIM / 128, E_DIM / 64, B_DIM), 256>>>(
        ao_buf, wp + 3 * E_DIM * E_DIM, bo, out);
}

// round 16
// speedup vs baseline: 5.6023x; 1.0929x over previous
#include <cuda_runtime.h>
#include <math_constants.h>
#include <cstdint>

#define E_DIM 256
#define T_DIM 1024
#define NH 8
#define HD 32
#define B_DIM 8
#define BHTOT 64   // B*NH

// Scratch (no allocations allowed). tf32-bit floats:
//  g_q, g_k : [bh][t][pp(d)]   g_v : [bh][d][t] (natural)   g_ao : [bh][t][pp(d)]
//  g_xt     : [tensor][b][t][pp(e)]  (transposed, paired, tf32)
//  g_wp     : [4][m][pp(k)]          (paired tf32 weights q,k,v,o)
__device__ float g_q [BHTOT * T_DIM * HD];
__device__ float g_k [BHTOT * T_DIM * HD];
__device__ float g_v [BHTOT * T_DIM * HD];
__device__ float g_ao[BHTOT * T_DIM * HD];
__device__ float g_xt[3u * B_DIM * T_DIM * E_DIM];
__device__ float g_wp[4 * E_DIM * E_DIM];

// ===========================================================================
__device__ __forceinline__ uint32_t f2tf(float x) {
    uint32_t r;
    asm("cvt.rna.tf32.f32 %0, %1;" : "=r"(r) : "f"(x));
    return r;
}
__device__ __forceinline__ float u2f(uint32_t x) { return __uint_as_float(x); }
__device__ __forceinline__ float ex2(float x) {
    float r;
    asm("ex2.approx.f32 %0, %1;" : "=f"(r) : "f"(x));
    return r;
}

__device__ __forceinline__ void mma16n8k8(float c[4], const uint32_t a[4],
                                          uint32_t b0, uint32_t b1) {
    asm volatile(
        "mma.sync.aligned.m16n8k8.row.col.f32.tf32.tf32.f32 "
        "{%0,%1,%2,%3}, {%4,%5,%6,%7}, {%8,%9}, {%0,%1,%2,%3};"
        : "+f"(c[0]), "+f"(c[1]), "+f"(c[2]), "+f"(c[3])
        : "r"(a[0]), "r"(a[1]), "r"(a[2]), "r"(a[3]), "r"(b0), "r"(b1));
}

// paired position: within aligned 8-blocks, order (0,4),(1,5),(2,6),(3,7)
__device__ __forceinline__ int pairpos(int k) {
    return (k & ~7) | ((k & 3) << 1) | ((k >> 2) & 1);
}
// inverse: source k for paired position p
__device__ __forceinline__ int srck(int p) {
    return (p & ~7) | ((p & 7) >> 1) | ((p & 1) << 2);
}

__device__ __forceinline__ uint32_t smem_u32(const void* p) {
    uint32_t a;
    asm("{ .reg .u64 t; cvta.to.shared.u64 t, %1; cvt.u32.u64 %0, t; }" : "=r"(a) : "l"(p));
    return a;
}
__device__ __forceinline__ void cp_async16(uint32_t dst, const void* src) {
    asm volatile("cp.async.ca.shared.global [%0], [%1], 16;" :: "r"(dst), "l"(src));
}
#define CP_COMMIT() asm volatile("cp.async.commit_group;" ::: "memory")
#define CP_WAIT0()  asm volatile("cp.async.wait_group 0;" ::: "memory")
#define CP_WAIT1()  asm volatile("cp.async.wait_group 1;" ::: "memory")

// ---------------------------------------------------------------------------
// Weight pre-convert: W[m][k] fp32 -> g_wp[wi][m][pp(k)] tf32 bits.
// ---------------------------------------------------------------------------
__global__ void wcvt_kernel(const float* __restrict__ Wq, const float* __restrict__ Wk,
                            const float* __restrict__ Wv, const float* __restrict__ Wo,
                            float* __restrict__ out)
{
    const float* W = (blockIdx.y == 0) ? Wq : (blockIdx.y == 1) ? Wk
                   : (blockIdx.y == 2) ? Wv : Wo;
    int m = blockIdx.x;
    int p = threadIdx.x * 4;
    const float* row = W + (size_t)m * E_DIM;
    float4 v;
    v.x = u2f(f2tf(row[srck(p + 0)]));
    v.y = u2f(f2tf(row[srck(p + 1)]));
    v.z = u2f(f2tf(row[srck(p + 2)]));
    v.w = u2f(f2tf(row[srck(p + 3)]));
    *(float4*)(out + ((size_t)blockIdx.y * E_DIM + m) * E_DIM + p) = v;
}

// ---------------------------------------------------------------------------
// Input transpose+convert: X[b][e][t] fp32 -> g_xt[tensor][b][t][pp(e)] tf32.
// ---------------------------------------------------------------------------
__global__ __launch_bounds__(256) void xt_kernel(
    const float* __restrict__ q, const float* __restrict__ k,
    const float* __restrict__ v, float* __restrict__ out)
{
    __shared__ float Ts[64][65];
    const int tz = blockIdx.z;
    const int tensor = tz >> 3, b = tz & 7;
    const float* X = (tensor == 0) ? q : (tensor == 1) ? k : v;
    const int e0 = blockIdx.y * 64, t0 = blockIdx.x * 64;
    const int tid = threadIdx.x;

    #pragma unroll
    for (int j = 0; j < 4; j++) {
        int e  = (tid >> 4) + j * 16;
        int t4 = (tid & 15) * 4;
        float4 val = *(const float4*)&X[((size_t)b * E_DIM + e0 + e) * T_DIM + t0 + t4];
        Ts[e][t4 + 0] = val.x; Ts[e][t4 + 1] = val.y;
        Ts[e][t4 + 2] = val.z; Ts[e][t4 + 3] = val.w;
    }
    __syncthreads();
    float* ob = out + (size_t)tensor * (B_DIM * T_DIM * E_DIM)
              + ((size_t)b * T_DIM + t0) * E_DIM + e0;
    #pragma unroll
    for (int j = 0; j < 8; j++) {
        int t = (tid >> 5) + j * 8;
        int e = tid & 31;
        ob[(size_t)t * E_DIM + pairpos(e)]      = u2f(f2tf(Ts[e][t]));
        ob[(size_t)t * E_DIM + pairpos(e + 32)] = u2f(f2tf(Ts[e + 32][t]));
    }
}

// ---------------------------------------------------------------------------
// QKV projection, cp.async double-buffered, all-tf32-paired operands.
// Block 256 (8 warps: 2m x 4n), tile M=64 x N=256, K-chunk 32, 8 chunks.
// Outputs: q/k paired [bh][t][pp(d)]; v natural [bh][d][t].
// ---------------------------------------------------------------------------
#define QKV_STAGE(KK0, BUF) do {                                               \
    _Pragma("unroll")                                                          \
    for (int j = 0; j < 8; j++) {                                              \
        int r = (tid >> 3) + j * 32;                                           \
        int seg = tid & 7;                                                     \
        cp_async16(xs_a + (((BUF) * 256 + r) * 40 + seg * 4) * 4,              \
                   Xb + (size_t)(n0 + r) * E_DIM + (KK0) + seg * 4);           \
    }                                                                          \
    _Pragma("unroll")                                                          \
    for (int j = 0; j < 2; j++) {                                              \
        int r = (tid >> 3) + j * 32;                                           \
        int seg = tid & 7;                                                     \
        cp_async16(ws_a + (((BUF) * 64 + r) * 40 + seg * 4) * 4,               \
                   Wm + (size_t)(m0 + r) * E_DIM + (KK0) + seg * 4);           \
    }                                                                          \
    CP_COMMIT();                                                               \
} while (0)

__global__ __launch_bounds__(256) void proj_qkv_kernel(
    const float* __restrict__ Xt, const float* __restrict__ Wp,
    const float* __restrict__ bq, const float* __restrict__ bk,
    const float* __restrict__ bv,
    float* __restrict__ Yq, float* __restrict__ Yk, float* __restrict__ Yv,
    float scale0)
{
    extern __shared__ float sm[];
    float* Xs  = sm;                 // [2][256][40]
    float* Wsm = sm + 2 * 256 * 40;  // [2][64][40]

    const int zz = blockIdx.z;
    const int b = zz & 7, which = zz >> 3;
    const float* Xb = Xt + (((size_t)which * B_DIM + b) * T_DIM) * E_DIM;
    const float* Wm = Wp + (size_t)which * E_DIM * E_DIM;
    const float* bias = (which == 0) ? bq : (which == 1) ? bk : bv;
    float* Y = (which == 0) ? Yq : (which == 1) ? Yk : Yv;
    const float scale = (which == 0) ? scale0 : 1.0f;

    const int m0 = blockIdx.y * 64;
    const int n0 = blockIdx.x * 256;
    const int tid = threadIdx.x;
    const int w = tid >> 5, l = tid & 31;
    const int wm = w >> 2, wn = w & 3;
    const int grp = l >> 2, tig = l & 3;

    const uint32_t xs_a = smem_u32(Xs);
    const uint32_t ws_a = smem_u32(Wsm);

    float acc[2][8][4];
    #pragma unroll
    for (int mt = 0; mt < 2; mt++)
        #pragma unroll
        for (int nt = 0; nt < 8; nt++)
            #pragma unroll
            for (int j = 0; j < 4; j++) acc[mt][nt][j] = 0.f;

    QKV_STAGE(0, 0);

    for (int c = 0; c < 8; c++) {
        const int buf = c & 1;
        if (c < 7) { QKV_STAGE((c + 1) * 32, buf ^ 1); CP_WAIT1(); }
        else       { CP_WAIT0(); }
        __syncthreads();

        #pragma unroll
        for (int ks = 0; ks < 4; ks++) {
            const float* wrow = &Wsm[(buf * 64 + wm * 32 + grp) * 40 + ks * 8 + tig * 2];
            uint2 aL0 = *(const uint2*)(wrow);
            uint2 aL1 = *(const uint2*)(wrow + 8 * 40);
            uint2 aH0 = *(const uint2*)(wrow + 16 * 40);
            uint2 aH1 = *(const uint2*)(wrow + 24 * 40);
            uint32_t a0[4] = {aL0.x, aL1.x, aL0.y, aL1.y};
            uint32_t a1[4] = {aH0.x, aH1.x, aH0.y, aH1.y};
            #pragma unroll
            for (int nt = 0; nt < 8; nt++) {
                uint2 bb = *(const uint2*)&Xs[(buf * 256 + wn * 64 + nt * 8 + grp) * 40
                                              + ks * 8 + tig * 2];
                mma16n8k8(acc[0][nt], a0, bb.x, bb.y);
                mma16n8k8(acc[1][nt], a1, bb.x, bb.y);
            }
        }
        __syncthreads();
    }

    // ---- epilogue (tf32 outputs) ----
    const int head = (m0 + wm * 32) >> 5;
    #pragma unroll
    for (int mt = 0; mt < 2; mt++) {
        int r0 = m0 + wm * 32 + mt * 16 + grp;
        int r1 = r0 + 8;
        float bv0 = bias[r0], bv1 = bias[r1];
        #pragma unroll
        for (int nt = 0; nt < 8; nt++) {
            int c = n0 + wn * 64 + nt * 8 + 2 * tig;
            float v00 = (acc[mt][nt][0] + bv0) * scale;
            float v01 = (acc[mt][nt][1] + bv0) * scale;
            float v10 = (acc[mt][nt][2] + bv1) * scale;
            float v11 = (acc[mt][nt][3] + bv1) * scale;
            uint32_t t00 = f2tf(v00), t01 = f2tf(v01);
            uint32_t t10 = f2tf(v10), t11 = f2tf(v11);
            if (which != 2) {
                // q/k: pair channels (d, d+4): partner lane = l ^ 16
                uint32_t u00 = __shfl_xor_sync(0xffffffffu, t00, 16);
                uint32_t u01 = __shfl_xor_sync(0xffffffffu, t01, 16);
                uint32_t u10 = __shfl_xor_sync(0xffffffffu, t10, 16);
                uint32_t u11 = __shfl_xor_sync(0xffffffffu, t11, 16);
                if (l < 16) {
                    float* y0 = Y + (((size_t)b * NH + head) * T_DIM + c) * HD;
                    float* y1 = y0 + HD;
                    int o0 = mt * 16 + 2 * grp;
                    int o1 = o0 + 8;
                    *(float2*)&y0[o0] = make_float2(u2f(t00), u2f(u00));
                    *(float2*)&y1[o0] = make_float2(u2f(t01), u2f(u01));
                    *(float2*)&y0[o1] = make_float2(u2f(t10), u2f(u10));
                    *(float2*)&y1[o1] = make_float2(u2f(t11), u2f(u11));
                }
            } else {
                // V: natural [bh][d][t], adjacent tokens -> direct float2
                int d0 = mt * 16 + grp, d1 = d0 + 8;
                float* z0 = Y + (((size_t)b * NH + head) * HD + d0) * T_DIM + c;
                float* z1 = Y + (((size_t)b * NH + head) * HD + d1) * T_DIM + c;
                *(float2*)z0 = make_float2(u2f(t00), u2f(t01));
                *(float2*)z1 = make_float2(u2f(t10), u2f(t11));
            }
        }
    }
}

// ---------------------------------------------------------------------------
// Output projection: Y[B,E,T] = Wo @ ao + bo.
// ---------------------------------------------------------------------------
__global__ __launch_bounds__(256) void proj_out_kernel(
    const float* __restrict__ X, const float* __restrict__ Wo_p,
    const float* __restrict__ bias, float* __restrict__ Y)
{
    __shared__ __align__(16) float Ws[64][40];
    const int b  = blockIdx.z;
    const int m0 = blockIdx.y * 64;
    const int n0 = blockIdx.x * 128;
    const int tid = threadIdx.x;
    const int w = tid >> 5, l = tid & 31;
    const int wm = w >> 2, wn = w & 3;
    const int grp = l >> 2, tig = l & 3;

    float acc[2][4][4];
    #pragma unroll
    for (int mt = 0; mt < 2; mt++)
        #pragma unroll
        for (int nt = 0; nt < 4; nt++)
            #pragma unroll
            for (int j = 0; j < 4; j++) acc[mt][nt][j] = 0.f;

    for (int k0 = 0; k0 < E_DIM; k0 += 32) {
        __syncthreads();
        #pragma unroll
        for (int j = 0; j < 2; j++) {
            int idx = tid + j * 256;
            int r = idx >> 3, c4 = (idx & 7) * 4;
            *(float4*)&Ws[r][c4] = *(const float4*)&Wo_p[(size_t)(m0 + r) * E_DIM + k0 + c4];
        }
        __syncthreads();

        const int head = k0 >> 5;
        const float* xb1 = X + (((size_t)b * NH + head) * T_DIM + n0 + wn * 32 + grp) * HD;

        #pragma unroll
        for (int ks = 0; ks < 4; ks++) {
            const float* wrow = &Ws[wm * 32 + grp][ks * 8 + tig * 2];
            uint2 aL0 = *(const uint2*)(wrow);
            uint2 aL1 = *(const uint2*)(wrow + 8 * 40);
            uint2 aH0 = *(const uint2*)(wrow + 16 * 40);
            uint2 aH1 = *(const uint2*)(wrow + 24 * 40);
            uint32_t a0[4] = {aL0.x, aL1.x, aL0.y, aL1.y};
            uint32_t a1[4] = {aH0.x, aH1.x, aH0.y, aH1.y};
            #pragma unroll
            for (int nt = 0; nt < 4; nt++) {
                uint2 bb = *(const uint2*)(xb1 + (size_t)nt * 8 * HD + ks * 8 + 2 * tig);
                mma16n8k8(acc[0][nt], a0, bb.x, bb.y);
                mma16n8k8(acc[1][nt], a1, bb.x, bb.y);
            }
        }
    }

    #pragma unroll
    for (int mt = 0; mt < 2; mt++) {
        int r0 = m0 + wm * 32 + mt * 16 + grp;
        int r1 = r0 + 8;
        float bv0 = bias[r0], bv1 = bias[r1];
        #pragma unroll
        for (int nt = 0; nt < 4; nt++) {
            int c = n0 + wn * 32 + nt * 8 + 2 * tig;
            *(float2*)&Y[((size_t)b * E_DIM + r0) * T_DIM + c] =
                make_float2(acc[mt][nt][0] + bv0, acc[mt][nt][1] + bv0);
            *(float2*)&Y[((size_t)b * E_DIM + r1) * T_DIM + c] =
                make_float2(acc[mt][nt][2] + bv1, acc[mt][nt][3] + bv1);
        }
    }
}

// ---------------------------------------------------------------------------
// Warp-MMA (tf32) flash attention — high-occupancy variant.
// Block 256 thr (8 warps), q-tile 128, warp owns 16 q rows (1 m-tile).
// log2-domain softmax (log2e folded into Q scale + mask preload, ex2.approx).
// P fed to MMA2 as RAW fp32 bits (HMMA.TF32 ignores low mantissa bits).
// ---------------------------------------------------------------------------
__global__ __launch_bounds__(256, 2) void attn_mma_kernel(
    const float* __restrict__ Q, const float* __restrict__ K,
    const float* __restrict__ V, const float* __restrict__ mask,
    float* __restrict__ O)
{
    __shared__ __align__(16) float Ks[64][40];     // [s][k paired]
    __shared__ __align__(16) float Vt[32][72];     // [d][s natural]

    const int bh  = blockIdx.y;
    const int q0  = blockIdx.x * 128;
    const int tid = threadIdx.x;
    const int w   = tid >> 5;
    const int l   = tid & 31;
    const int grp = l >> 2;
    const int tig = l & 3;

    const uint32_t ks_a = smem_u32(&Ks[0][0]);
    const uint32_t vt_a = smem_u32(&Vt[0][0]);

    const float L2E = 1.4426950408889634f;

    // ---- Q fragments: direct paired loads (16 q rows per warp) ----
    uint32_t qa[4][4];
    {
        const float* Qb = Q + ((size_t)bh * T_DIM + q0 + w * 16) * HD;
        #pragma unroll
        for (int ks = 0; ks < 4; ks++) {
            uint2 p0 = *(const uint2*)(Qb + (size_t)grp       * HD + ks * 8 + 2 * tig);
            uint2 p1 = *(const uint2*)(Qb + (size_t)(grp + 8) * HD + ks * 8 + 2 * tig);
            qa[ks][0] = p0.x; qa[ks][1] = p1.x;
            qa[ks][2] = p0.y; qa[ks][3] = p1.y;
        }
    }

    float o_[4][4];
    #pragma unroll
    for (int nt = 0; nt < 4; nt++)
        #pragma unroll
        for (int j = 0; j < 4; j++) o_[nt][j] = 0.f;

    float m0r = -CUDART_INF_F, m1r = -CUDART_INF_F, l0r = 0.f, l1r = 0.f;

    const float* mr0 = mask + (size_t)(q0 + w * 16 + grp) * T_DIM;
    const float* mr1 = mr0 + 8 * T_DIM;

    for (int s0 = 0; s0 < T_DIM; s0 += 64) {
        __syncthreads();   // prior tile's smem reads complete
        // ---- cp.async stage K (64x32 paired): 2 x 16B per thread ----
        #pragma unroll
        for (int j = 0; j < 2; j++) {
            int idx = tid + j * 256;
            int r = idx >> 3, seg = idx & 7;
            cp_async16(ks_a + (r * 40 + seg * 4) * 4,
                       K + ((size_t)bh * T_DIM + s0 + r) * HD + seg * 4);
        }
        // ---- cp.async stage V (32d x 64s natural): 2 x 16B per thread ----
        #pragma unroll
        for (int j = 0; j < 2; j++) {
            int idx = tid + j * 256;
            int d = idx >> 4, seg = idx & 15;
            cp_async16(vt_a + (d * 72 + seg * 4) * 4,
                       V + ((size_t)bh * HD + d) * T_DIM + s0 + seg * 4);
        }
        CP_COMMIT();

        // ---- mask preload (scaled to log2 domain) into MMA1 accumulators ----
        float sc[8][4];
        #pragma unroll
        for (int nt = 0; nt < 8; nt++) {
            float2 mk0 = __ldg((const float2*)&mr0[s0 + nt * 8 + 2 * tig]);
            float2 mk1 = __ldg((const float2*)&mr1[s0 + nt * 8 + 2 * tig]);
            sc[nt][0] = mk0.x * L2E; sc[nt][1] = mk0.y * L2E;
            sc[nt][2] = mk1.x * L2E; sc[nt][3] = mk1.y * L2E;
        }

        CP_WAIT0();
        __syncthreads();

        // ---- MMA1: sc += Q' K^T  (Q' pre-scaled by hd^-0.5 * log2e) ----
        #pragma unroll
        for (int nt = 0; nt < 8; nt++)
            #pragma unroll
            for (int ks = 0; ks < 4; ks++) {
                uint2 bb = *(const uint2*)&Ks[nt * 8 + grp][ks * 8 + tig * 2];
                mma16n8k8(sc[nt], qa[ks], bb.x, bb.y);
            }

        // ---- row max (log2 domain) ----
        float mx0 = -CUDART_INF_F, mx1 = -CUDART_INF_F;
        #pragma unroll
        for (int nt = 0; nt < 8; nt++) {
            mx0 = fmaxf(mx0, fmaxf(sc[nt][0], sc[nt][1]));
            mx1 = fmaxf(mx1, fmaxf(sc[nt][2], sc[nt][3]));
        }
        mx0 = fmaxf(mx0, __shfl_xor_sync(0xffffffffu, mx0, 1));
        mx0 = fmaxf(mx0, __shfl_xor_sync(0xffffffffu, mx0, 2));
        mx1 = fmaxf(mx1, __shfl_xor_sync(0xffffffffu, mx1, 1));
        mx1 = fmaxf(mx1, __shfl_xor_sync(0xffffffffu, mx1, 2));

        float mn0 = fmaxf(m0r, mx0), mn1 = fmaxf(m1r, mx1);
        float corr0 = ex2(m0r - mn0), corr1 = ex2(m1r - mn1);
        m0r = mn0; m1r = mn1;
        float sum0 = 0.f, sum1 = 0.f;

        // ---- exp2 in place (P stays in sc registers) ----
        #pragma unroll
        for (int nt = 0; nt < 8; nt++) {
            float p0 = ex2(sc[nt][0] - mn0);
            float p1 = ex2(sc[nt][1] - mn0);
            float p2 = ex2(sc[nt][2] - mn1);
            float p3 = ex2(sc[nt][3] - mn1);
            sum0 += p0 + p1;  sum1 += p2 + p3;
            sc[nt][0] = p0; sc[nt][1] = p1;
            sc[nt][2] = p2; sc[nt][3] = p3;
        }
        sum0 += __shfl_xor_sync(0xffffffffu, sum0, 1);
        sum0 += __shfl_xor_sync(0xffffffffu, sum0, 2);
        sum1 += __shfl_xor_sync(0xffffffffu, sum1, 1);
        sum1 += __shfl_xor_sync(0xffffffffu, sum1, 2);
        l0r = l0r * corr0 + sum0;
        l1r = l1r * corr1 + sum1;

        #pragma unroll
        for (int nt = 0; nt < 4; nt++) {
            o_[nt][0] *= corr0; o_[nt][1] *= corr0;
            o_[nt][2] *= corr1; o_[nt][3] *= corr1;
        }

        // ---- MMA2: O(16x32) += P(16x64) V(64x32) — P as raw fp32 bits ----
        #pragma unroll
        for (int ks = 0; ks < 8; ks++) {
            uint32_t a0[4] = {__float_as_uint(sc[ks][0]), __float_as_uint(sc[ks][2]),
                              __float_as_uint(sc[ks][1]), __float_as_uint(sc[ks][3])};
            #pragma unroll
            for (int nt = 0; nt < 4; nt++) {
                uint2 bb = *(const uint2*)&Vt[nt * 8 + grp][ks * 8 + tig * 2];
                mma16n8k8(o_[nt], a0, bb.x, bb.y);
            }
        }
    }

    // ---- epilogue: ao tf32-paired [bh][t][pp(d)] ----
    float i0 = 1.f / l0r, i1 = 1.f / l1r;
    #pragma unroll
    for (int nt = 0; nt < 4; nt++) {
        uint32_t t0 = f2tf(o_[nt][0] * i0), t1 = f2tf(o_[nt][1] * i0);
        uint32_t t2 = f2tf(o_[nt][2] * i1), t3 = f2tf(o_[nt][3] * i1);
        uint32_t u0 = __shfl_xor_sync(0xffffffffu, t0, 2);
        uint32_t u1 = __shfl_xor_sync(0xffffffffu, t1, 2);
        uint32_t u2 = __shfl_xor_sync(0xffffffffu, t2, 2);
        uint32_t u3 = __shfl_xor_sync(0xffffffffu, t3, 2);
        if (tig < 2) {
            size_t r0 = (size_t)bh * T_DIM + q0 + w * 16 + grp;
            float* z0 = O + r0 * HD + nt * 8 + 4 * tig;
            float* z1 = z0 + 8 * HD;
            *(float4*)z0 = make_float4(u2f(t0), u2f(u0), u2f(t1), u2f(u1));
            *(float4*)z1 = make_float4(u2f(t2), u2f(u2), u2f(t3), u2f(u3));
        }
    }
}

// ---------------------------------------------------------------------------
extern "C" void kernel_launch(void* const* d_in, const int* in_sizes, int n_in,
                              void* d_out, int out_size)
{
    // metadata order: 0:query 1:key 2:value 3:attn_mask
    //                 4:Wq 5:Wk 6:Wv 7:Wo  8:bq 9:bk 10:bv 11:bo
    const float* query = (const float*)d_in[0];
    const float* key   = (const float*)d_in[1];
    const float* value = (const float*)d_in[2];
    const float* mask  = (const float*)d_in[3];
    const float* Wq    = (const float*)d_in[4];
    const float* Wk    = (const float*)d_in[5];
    const float* Wv    = (const float*)d_in[6];
    const float* Wo    = (const float*)d_in[7];
    const float* bq    = (const float*)d_in[8];
    const float* bk    = (const float*)d_in[9];
    const float* bv    = (const float*)d_in[10];
    const float* bo    = (const float*)d_in[11];
    float* out = (float*)d_out;

    static float *q_buf = nullptr, *k_buf, *v_buf, *ao_buf, *xt, *wp;
    if (!q_buf) {
        void* p;
        cudaGetSymbolAddress(&p, g_q);  q_buf  = (float*)p;
        cudaGetSymbolAddress(&p, g_k);  k_buf  = (float*)p;
        cudaGetSymbolAddress(&p, g_v);  v_buf  = (float*)p;
        cudaGetSymbolAddress(&p, g_ao); ao_buf = (float*)p;
        cudaGetSymbolAddress(&p, g_xt); xt = (float*)p;
        cudaGetSymbolAddress(&p, g_wp); wp = (float*)p;
        cudaFuncSetAttribute(proj_qkv_kernel,
                             cudaFuncAttributeMaxDynamicSharedMemorySize, 102400);
    }

    // 32^-0.5 * log2(e): log2-domain softmax, folded into Q projection
    const float scale = 0.17677669529663687f * 1.4426950408889634f;

    // 1) weight pre-convert (paired tf32)
    wcvt_kernel<<<dim3(E_DIM, 4), E_DIM / 4>>>(Wq, Wk, Wv, Wo, wp);

    // 2) input transpose+convert -> [tensor][b][t][pp(e)]
    xt_kernel<<<dim3(T_DIM / 64, E_DIM / 64, 24), 256>>>(query, key, value, xt);

    // 3) QKV projections (cp.async double-buffered)
    proj_qkv_kernel<<<dim3(T_DIM / 256, E_DIM / 64, 24), 256, 102400>>>(
        xt, wp, bq, bk, bv, q_buf, k_buf, v_buf, scale);

    // 4) attention (8 warps / 128 q per block)
    attn_mma_kernel<<<dim3(T_DIM / 128, BHTOT), 256>>>(q_buf, k_buf, v_buf, mask, ao_buf);

    // 5) output projection
    proj_out_kernel<<<dim3(T_DIM / 128, E_DIM / 64, B_DIM), 256>>>(
        ao_buf, wp + 3 * E_DIM * E_DIM, bo, out);
}